// round 4
// baseline (speedup 1.0000x reference)
#include <cuda_runtime.h>

#define BB 4
#define TT 4096
#define CE 512
#define DHH 64
#define QTILE 128
#define NQT (TT / QTILE)          // 32
#define KTW 64                    // k-tile width
#define KCHUNK 4                  // k-tiles per split unit
#define MAXSPLIT 16
#define UNITS_PER_B 272           // sum_{qi=0}^{31} ceil((2qi+2)/4)

typedef unsigned long long u64;

// Scratch (__device__ globals, allocation-free)
__device__ float g_Q[BB * TT * DHH];
__device__ float g_K[BB * TT * DHH];
__device__ float g_V[BB * TT * DHH];
__device__ float g_Op[(size_t)BB * NQT * MAXSPLIT * QTILE * DHH];
__device__ float g_L[BB * NQT * MAXSPLIT * QTILE];

// ---- packed f32x2 helpers (Blackwell) ----
__device__ __forceinline__ u64 pk2(float lo, float hi) {
    u64 r; asm("mov.b64 %0,{%1,%2};" : "=l"(r) : "f"(lo), "f"(hi)); return r;
}
__device__ __forceinline__ void fma2(u64& d, u64 a, u64 b) {
    asm("fma.rn.f32x2 %0,%1,%2,%0;" : "+l"(d) : "l"(a), "l"(b));
}
__device__ __forceinline__ float2 up2(u64 v) {
    float2 f; asm("mov.b64 {%0,%1},%2;" : "=f"(f.x), "=f"(f.y) : "l"(v)); return f;
}

// ---------------------------------------------------------------------------
// QKV projection, pack-free inner loop.
// grid (128, 3), 256 threads. Tile 128 rows x 64 cols, 8x4 per thread.
// W stored in smem as DUPLICATED u64 pairs -> B operand loads packed directly.
// ---------------------------------------------------------------------------
__global__ __launch_bounds__(256) void qkv_kernel(
    const float* __restrict__ x,
    const float* __restrict__ Wq, const float* __restrict__ bq,
    const float* __restrict__ Wk, const float* __restrict__ bk,
    const float* __restrict__ Wv, const float* __restrict__ bv)
{
    __shared__ float xs[32 * 128];   // [k][r] swizzled
    __shared__ u64   ws[32 * 64];    // [k][n] dup-packed, swizzled

    const float* W; const float* bias; float* out;
    if (blockIdx.y == 0)      { W = Wq; bias = bq; out = g_Q; }
    else if (blockIdx.y == 1) { W = Wk; bias = bk; out = g_K; }
    else                      { W = Wv; bias = bv; out = g_V; }

    const int tid = threadIdx.x;
    const int tx = tid & 15, ty = tid >> 4;
    const int row0 = blockIdx.x * 128;

    u64 acc[4][4];
    #pragma unroll
    for (int i = 0; i < 4; i++)
        #pragma unroll
        for (int j = 0; j < 4; j++) acc[i][j] = 0ull;

    float4 xr[4], wr[2];

    auto loadChunk = [&](int k0) {
        #pragma unroll
        for (int p = 0; p < 4; p++) {
            int idx = tid + p * 256;              // 128 rows x 8 float4
            int m = idx >> 3, kq = idx & 7;
            xr[p] = *(const float4*)(x + (size_t)(row0 + m) * CE + k0 + 4 * kq);
        }
        #pragma unroll
        for (int p = 0; p < 2; p++) {
            int idx = tid + p * 256;              // 64 rows x 8 float4
            int n = idx >> 3, kq = idx & 7;
            wr[p] = *(const float4*)(W + (size_t)n * CE + k0 + 4 * kq);
        }
    };
    auto storeChunk = [&]() {
        #pragma unroll
        for (int p = 0; p < 4; p++) {
            int idx = tid + p * 256;
            int m = idx >> 3, kq = idx & 7;
            int cc = (((m >> 2) ^ kq) << 2) + (m & 3);
            int rr = 4 * kq * 128;
            xs[rr + cc]       = xr[p].x; xs[rr + 128 + cc] = xr[p].y;
            xs[rr + 256 + cc] = xr[p].z; xs[rr + 384 + cc] = xr[p].w;
        }
        #pragma unroll
        for (int p = 0; p < 2; p++) {
            int idx = tid + p * 256;
            int n = idx >> 3, kq = idx & 7;
            float v[4] = {wr[p].x, wr[p].y, wr[p].z, wr[p].w};
            #pragma unroll
            for (int e = 0; e < 4; e++) {
                int k = 4 * kq + e;
                ws[k * 64 + ((((n >> 2) ^ k) & 15) << 2) + (n & 3)] = pk2(v[e], v[e]);
            }
        }
    };

    loadChunk(0);
    storeChunk();
    __syncthreads();

    for (int c = 0; c < 16; c++) {
        if (c < 15) loadChunk(32 * (c + 1));

        #pragma unroll 2
        for (int dg = 0; dg < 8; dg++) {
            const float* xb = xs + 4 * dg * 128;
            const u64*   wb = ws + 4 * dg * 64;
            const int oa0 = ((2 * ty) ^ dg) << 2;
            const int oa1 = ((2 * ty + 1) ^ dg) << 2;
            #pragma unroll
            for (int e = 0; e < 4; e++) {
                ulonglong2 A0 = *(const ulonglong2*)(xb + e * 128 + oa0);
                ulonglong2 A1 = *(const ulonglong2*)(xb + e * 128 + oa1);
                int gb = ((tx ^ (4 * dg + e)) & 15) << 2;
                ulonglong2 B0 = *(const ulonglong2*)(wb + e * 64 + gb);
                ulonglong2 B1 = *(const ulonglong2*)(wb + e * 64 + gb + 2);
                fma2(acc[0][0], A0.x, B0.x); fma2(acc[0][1], A0.x, B0.y);
                fma2(acc[0][2], A0.x, B1.x); fma2(acc[0][3], A0.x, B1.y);
                fma2(acc[1][0], A0.y, B0.x); fma2(acc[1][1], A0.y, B0.y);
                fma2(acc[1][2], A0.y, B1.x); fma2(acc[1][3], A0.y, B1.y);
                fma2(acc[2][0], A1.x, B0.x); fma2(acc[2][1], A1.x, B0.y);
                fma2(acc[2][2], A1.x, B1.x); fma2(acc[2][3], A1.x, B1.y);
                fma2(acc[3][0], A1.y, B0.x); fma2(acc[3][1], A1.y, B0.y);
                fma2(acc[3][2], A1.y, B1.x); fma2(acc[3][3], A1.y, B1.y);
            }
        }
        __syncthreads();
        if (c < 15) { storeChunk(); __syncthreads(); }
    }

    const float4 b4 = *(const float4*)(bias + 4 * tx);
    #pragma unroll
    for (int i2 = 0; i2 < 4; i2++) {
        float2 f0 = up2(acc[i2][0]), f1 = up2(acc[i2][1]);
        float2 f2 = up2(acc[i2][2]), f3 = up2(acc[i2][3]);
        int r0 = row0 + 8 * ty + 2 * i2;
        *(float4*)(out + (size_t)r0 * DHH + 4 * tx) =
            make_float4(f0.x + b4.x, f1.x + b4.y, f2.x + b4.z, f3.x + b4.w);
        *(float4*)(out + (size_t)(r0 + 1) * DHH + 4 * tx) =
            make_float4(f0.y + b4.x, f1.y + b4.y, f2.y + b4.z, f3.y + b4.w);
    }
}

// ---------------------------------------------------------------------------
// Split-K causal flash attention (no max-tracking: |S| < ~50, raw exp safe).
// BLOCK_M=128, BLOCK_N=64, 256 threads, 8x4/thread FFMA2.
// V double-buffered; K/V prefetched to regs; 2 syncthreads per k-tile.
// ---------------------------------------------------------------------------
__global__ __launch_bounds__(256, 2) void attn_kernel()
{
    const int b = blockIdx.y;
    int xx = blockIdx.x, qi = 0, split = 0;
    for (int q = NQT - 1; q >= 0; q--) {
        int ns = (2 * q + 2 + KCHUNK - 1) / KCHUNK;
        if (xx < ns) { qi = q; split = xx; break; }
        xx -= ns;
    }
    const int nkt = 2 * qi + 2;
    const int kt0 = split * KCHUNK;
    const int kt1 = min(kt0 + KCHUNK, nkt);
    const int q0 = qi * QTILE;

    const float* Q = g_Q + (size_t)b * TT * DHH;
    const float* K = g_K + (size_t)b * TT * DHH;
    const float* V = g_V + (size_t)b * TT * DHH;

    extern __shared__ float sm[];
    float* qT = sm;                      // [d=64][r=128] swizzled   32KB
    float* kT = sm + 8192;               // [d=64][c=64]  swizzled   16KB
    float* vs = kT + 4096;               // 2 x [c=64][d=64]         32KB
    float* pT = vs + 2 * 4096;           // [c=64][r=128] swizzled   32KB

    const int tid = threadIdx.x;
    const int tx = tid & 15, ty = tid >> 4;

    // Q tile (128x64), transposed + swizzled
    #pragma unroll
    for (int p = 0; p < 8; p++) {
        int idx = tid + p * 256;
        int m = idx >> 4, dq = idx & 15;
        float4 v4 = *(const float4*)(Q + (size_t)(q0 + m) * DHH + 4 * dq);
        int cc = ((((m >> 2) ^ dq) & 31) << 2) + (m & 3);
        int rr = 4 * dq * 128;
        qT[rr + cc]       = v4.x; qT[rr + 128 + cc] = v4.y;
        qT[rr + 256 + cc] = v4.z; qT[rr + 384 + cc] = v4.w;
    }

    float4 kr[4], vr[4];
    auto loadKV = [&](int kt) {
        const int k0 = kt * KTW;
        #pragma unroll
        for (int p = 0; p < 4; p++) {
            int idx = tid + p * 256;
            int m = idx >> 4, dq = idx & 15;
            kr[p] = *(const float4*)(K + (size_t)(k0 + m) * DHH + 4 * dq);
            vr[p] = *(const float4*)(V + (size_t)(k0 + m) * DHH + 4 * dq);
        }
    };
    auto storeKV = [&](int buf) {
        float* vb = vs + buf * 4096;
        #pragma unroll
        for (int p = 0; p < 4; p++) {
            int idx = tid + p * 256;
            int m = idx >> 4, dq = idx & 15;
            int cc = ((((m >> 2) ^ dq) & 15) << 2) + (m & 3);
            int rr = 4 * dq * 64;
            kT[rr + cc]       = kr[p].x; kT[rr + 64 + cc]  = kr[p].y;
            kT[rr + 128 + cc] = kr[p].z; kT[rr + 192 + cc] = kr[p].w;
            *(float4*)(vb + m * 64 + ((dq ^ ((m >> 2) & 15)) << 2)) = vr[p];
        }
    };

    loadKV(kt0);
    storeKV(0);

    u64 o2[4][4];
    #pragma unroll
    for (int i = 0; i < 4; i++)
        #pragma unroll
        for (int j = 0; j < 4; j++) o2[i][j] = 0ull;
    float lpart[8];
    #pragma unroll
    for (int i = 0; i < 8; i++) lpart[i] = 0.0f;

    __syncthreads();

    for (int kt = kt0; kt < kt1; kt++) {
        const int k0 = kt * KTW;
        const int cur = (kt - kt0) & 1;
        const bool more = (kt + 1 < kt1);

        if (more) loadKV(kt + 1);   // LDGs in flight through the S phase

        // S = Q K^T
        u64 s2[4][4];
        #pragma unroll
        for (int i = 0; i < 4; i++)
            #pragma unroll
            for (int j = 0; j < 4; j++) s2[i][j] = 0ull;

        #pragma unroll 4
        for (int dg = 0; dg < 16; dg++) {
            const float* qb = qT + 4 * dg * 128;
            const float* kb = kT + 4 * dg * 64;
            const int o0 = ((2 * ty) ^ dg) << 2;
            const int o1 = ((2 * ty + 1) ^ dg) << 2;
            const int ob = (tx ^ dg) << 2;
            #pragma unroll
            for (int e = 0; e < 4; e++) {
                ulonglong2 A0 = *(const ulonglong2*)(qb + e * 128 + o0);
                ulonglong2 A1 = *(const ulonglong2*)(qb + e * 128 + o1);
                float4 bk = *(const float4*)(kb + e * 64 + ob);
                u64 b0 = pk2(bk.x, bk.x), b1 = pk2(bk.y, bk.y);
                u64 b2 = pk2(bk.z, bk.z), b3 = pk2(bk.w, bk.w);
                fma2(s2[0][0], A0.x, b0); fma2(s2[0][1], A0.x, b1);
                fma2(s2[0][2], A0.x, b2); fma2(s2[0][3], A0.x, b3);
                fma2(s2[1][0], A0.y, b0); fma2(s2[1][1], A0.y, b1);
                fma2(s2[1][2], A0.y, b2); fma2(s2[1][3], A0.y, b3);
                fma2(s2[2][0], A1.x, b0); fma2(s2[2][1], A1.x, b1);
                fma2(s2[2][2], A1.x, b2); fma2(s2[2][3], A1.x, b3);
                fma2(s2[3][0], A1.y, b0); fma2(s2[3][1], A1.y, b1);
                fma2(s2[3][2], A1.y, b2); fma2(s2[3][3], A1.y, b3);
            }
        }

        // unpack, mask (diagonal only), exp, row sums
        float p[8][4];
        #pragma unroll
        for (int i2 = 0; i2 < 4; i2++)
            #pragma unroll
            for (int j = 0; j < 4; j++) {
                float2 f = up2(s2[i2][j]);
                p[2 * i2][j] = f.x; p[2 * i2 + 1][j] = f.y;
            }
        if (kt >= 2 * qi) {
            #pragma unroll
            for (int i = 0; i < 8; i++)
                #pragma unroll
                for (int j = 0; j < 4; j++)
                    if (k0 + 4 * tx + j > q0 + 8 * ty + i) p[i][j] = -1e30f;
        }
        #pragma unroll
        for (int i = 0; i < 8; i++) {
            #pragma unroll
            for (int j = 0; j < 4; j++) p[i][j] = __expf(p[i][j]);
            lpart[i] += (p[i][0] + p[i][1]) + (p[i][2] + p[i][3]);
        }

        __syncthreads();   // S done (kT free), prev PV done (pT, old vs free)

        #pragma unroll
        for (int j = 0; j < 4; j++) {
            int c = 4 * tx + j;
            float* pb = pT + c * 128;
            *(float4*)(pb + (((2 * ty) ^ tx) << 2))     = make_float4(p[0][j], p[1][j], p[2][j], p[3][j]);
            *(float4*)(pb + (((2 * ty + 1) ^ tx) << 2)) = make_float4(p[4][j], p[5][j], p[6][j], p[7][j]);
        }
        if (more) storeKV(1 - cur);

        __syncthreads();   // pT + next K/V visible

        // O += P V
        const float* vbuf = vs + cur * 4096;
        #pragma unroll 4
        for (int cg = 0; cg < 16; cg++) {
            const float* pb = pT + 4 * cg * 128;
            const float* vb = vbuf + 4 * cg * 64;
            const int o0 = ((2 * ty) ^ cg) << 2;
            const int o1 = ((2 * ty + 1) ^ cg) << 2;
            const int ob = (tx ^ cg) << 2;
            #pragma unroll
            for (int e = 0; e < 4; e++) {
                ulonglong2 A0 = *(const ulonglong2*)(pb + e * 128 + o0);
                ulonglong2 A1 = *(const ulonglong2*)(pb + e * 128 + o1);
                float4 vv = *(const float4*)(vb + e * 64 + ob);
                u64 b0 = pk2(vv.x, vv.x), b1 = pk2(vv.y, vv.y);
                u64 b2 = pk2(vv.z, vv.z), b3 = pk2(vv.w, vv.w);
                fma2(o2[0][0], A0.x, b0); fma2(o2[0][1], A0.x, b1);
                fma2(o2[0][2], A0.x, b2); fma2(o2[0][3], A0.x, b3);
                fma2(o2[1][0], A0.y, b0); fma2(o2[1][1], A0.y, b1);
                fma2(o2[1][2], A0.y, b2); fma2(o2[1][3], A0.y, b3);
                fma2(o2[2][0], A1.x, b0); fma2(o2[2][1], A1.x, b1);
                fma2(o2[2][2], A1.x, b2); fma2(o2[2][3], A1.x, b3);
                fma2(o2[3][0], A1.y, b0); fma2(o2[3][1], A1.y, b1);
                fma2(o2[3][2], A1.y, b2); fma2(o2[3][3], A1.y, b3);
            }
        }
    }

    #pragma unroll
    for (int i = 0; i < 8; i++) {
        #pragma unroll
        for (int o = 1; o < 16; o <<= 1)
            lpart[i] += __shfl_xor_sync(0xffffffffu, lpart[i], o);
    }

    const size_t ubase = (size_t)(b * NQT + qi) * MAXSPLIT + split;
    float* Op = g_Op + ubase * (QTILE * DHH);
    #pragma unroll
    for (int i2 = 0; i2 < 4; i2++) {
        float2 f0 = up2(o2[i2][0]), f1 = up2(o2[i2][1]);
        float2 f2 = up2(o2[i2][2]), f3 = up2(o2[i2][3]);
        int r0 = 8 * ty + 2 * i2;
        *(float4*)(Op + (size_t)r0 * DHH + 4 * tx)       = make_float4(f0.x, f1.x, f2.x, f3.x);
        *(float4*)(Op + (size_t)(r0 + 1) * DHH + 4 * tx) = make_float4(f0.y, f1.y, f2.y, f3.y);
    }
    if (tx == 0) {
        #pragma unroll
        for (int i = 0; i < 8; i++)
            g_L[ubase * QTILE + 8 * ty + i] = lpart[i];
    }
}

// ---------------------------------------------------------------------------
// Combine partials: out = 8 * sum_s O_s / sum_s l_s
// ---------------------------------------------------------------------------
__global__ __launch_bounds__(256) void combine_kernel(float* __restrict__ out)
{
    const int qi = blockIdx.x, b = blockIdx.y;
    const int ns = (2 * qi + 2 + KCHUNK - 1) / KCHUNK;
    const int tid = threadIdx.x;
    const int r = tid >> 1;
    const int c0 = (tid & 1) * 32;
    const size_t tbase = (size_t)(b * NQT + qi) * MAXSPLIT;

    float acc[32];
    #pragma unroll
    for (int k = 0; k < 32; k++) acc[k] = 0.0f;
    float l = 0.0f;

    for (int s = 0; s < ns; s++) {
        const float* Op = g_Op + (tbase + s) * (size_t)(QTILE * DHH) + (size_t)r * DHH + c0;
        l += g_L[(tbase + s) * QTILE + r];
        #pragma unroll
        for (int j4 = 0; j4 < 8; j4++) {
            float4 v = *(const float4*)(Op + 4 * j4);
            acc[4 * j4 + 0] += v.x; acc[4 * j4 + 1] += v.y;
            acc[4 * j4 + 2] += v.z; acc[4 * j4 + 3] += v.w;
        }
    }

    const float inv = 8.0f / l;
    float* o = out + ((size_t)b * TT + (size_t)qi * QTILE + r) * DHH + c0;
    #pragma unroll
    for (int j4 = 0; j4 < 8; j4++)
        *(float4*)(o + 4 * j4) = make_float4(acc[4 * j4] * inv, acc[4 * j4 + 1] * inv,
                                             acc[4 * j4 + 2] * inv, acc[4 * j4 + 3] * inv);
}

// ---------------------------------------------------------------------------
extern "C" void kernel_launch(void* const* d_in, const int* in_sizes, int n_in,
                              void* d_out, int out_size)
{
    (void)in_sizes; (void)n_in; (void)out_size;
    const float* x  = (const float*)d_in[0];
    const float* Wq = (const float*)d_in[1];
    const float* bq = (const float*)d_in[2];
    const float* Wk = (const float*)d_in[3];
    const float* bk = (const float*)d_in[4];
    const float* Wv = (const float*)d_in[5];
    const float* bv = (const float*)d_in[6];
    float* out = (float*)d_out;

    qkv_kernel<<<dim3(BB * TT / 128, 3), 256>>>(x, Wq, bq, Wk, bk, Wv, bv);

    const int smem = (8192 + 4096 + 2 * 4096 + 8192) * (int)sizeof(float); // 112KB
    cudaFuncSetAttribute(attn_kernel, cudaFuncAttributeMaxDynamicSharedMemorySize, smem);
    attn_kernel<<<dim3(UNITS_PER_B, BB), 256, smem>>>();

    combine_kernel<<<dim3(NQT, BB), 256>>>(out);
}

// round 6
// speedup vs baseline: 1.2655x; 1.2655x over previous
#include <cuda_runtime.h>

#define BB 4
#define TT 4096
#define CE 512
#define DHH 64
#define QTILE 128
#define NQT (TT / QTILE)          // 32
#define KTW 64                    // k-tile width
#define KCHUNK 4                  // k-tiles per split unit
#define MAXSPLIT 16
#define UNITS_PER_B 272           // sum_{qi=0}^{31} ceil((2qi+2)/4)

typedef unsigned long long u64;

// Scratch (__device__ globals, allocation-free)
// Q, K stored TRANSPOSED per batch: [b][d][t]  (d*TT + t). V row-major [b][t][d].
__device__ float g_Q[BB * TT * DHH];
__device__ float g_K[BB * TT * DHH];
__device__ float g_V[BB * TT * DHH];
__device__ float g_Op[(size_t)BB * NQT * MAXSPLIT * QTILE * DHH];
__device__ float g_L[BB * NQT * MAXSPLIT * QTILE];

// ---- packed f32x2 helpers (Blackwell) ----
__device__ __forceinline__ u64 pk2(float lo, float hi) {
    u64 r; asm("mov.b64 %0,{%1,%2};" : "=l"(r) : "f"(lo), "f"(hi)); return r;
}
__device__ __forceinline__ void fma2(u64& d, u64 a, u64 b) {
    asm("fma.rn.f32x2 %0,%1,%2,%0;" : "+l"(d) : "l"(a), "l"(b));
}
__device__ __forceinline__ float2 up2(u64 v) {
    float2 f; asm("mov.b64 {%0,%1},%2;" : "=f"(f.x), "=f"(f.y) : "l"(v)); return f;
}

// ---- cp.async helpers ----
__device__ __forceinline__ void cpa16(unsigned smem, const float* g) {
    asm volatile("cp.async.cg.shared.global [%0], [%1], 16;" :: "r"(smem), "l"(g));
}
__device__ __forceinline__ void cpa_commit() {
    asm volatile("cp.async.commit_group;");
}
template <int N> __device__ __forceinline__ void cpa_wait() {
    asm volatile("cp.async.wait_group %0;" :: "n"(N));
}

// ---------------------------------------------------------------------------
// QKV projection (round-2 proven inner loop).
// grid (256, 3), 256 threads, 64x64 tile, 4x4 per thread (row-paired FFMA2).
// Epilogue: Q,K written transposed [d][t]; V row-major.
// ---------------------------------------------------------------------------
__global__ __launch_bounds__(256) void qkv_kernel(
    const float* __restrict__ x,
    const float* __restrict__ Wq, const float* __restrict__ bq,
    const float* __restrict__ Wk, const float* __restrict__ bk,
    const float* __restrict__ Wv, const float* __restrict__ bv)
{
    __shared__ float xT[32 * 64];
    __shared__ float wT[32 * 64];

    const float* W; const float* bias; float* out; int transposed;
    if (blockIdx.y == 0)      { W = Wq; bias = bq; out = g_Q; transposed = 1; }
    else if (blockIdx.y == 1) { W = Wk; bias = bk; out = g_K; transposed = 1; }
    else                      { W = Wv; bias = bv; out = g_V; transposed = 0; }

    const int tid = threadIdx.x;
    const int tx = tid & 15, ty = tid >> 4;
    const int row0 = blockIdx.x * 64;

    u64 acc2[2][4];
    #pragma unroll
    for (int i = 0; i < 2; i++)
        #pragma unroll
        for (int j = 0; j < 4; j++) acc2[i][j] = 0ull;

    for (int k0 = 0; k0 < CE; k0 += 32) {
        __syncthreads();
        #pragma unroll
        for (int p = 0; p < 2; p++) {
            int idx = tid + p * 256;            // 64 rows x 8 float4
            int m = idx >> 3, kq = idx & 7;
            float4 xv = *(const float4*)(x + (size_t)(row0 + m) * CE + k0 + 4 * kq);
            float4 wv = *(const float4*)(W + (size_t)m * CE + k0 + 4 * kq);
            int cc = ((((m >> 2) ^ kq) << 2) + (m & 3));
            int rr = 4 * kq * 64;
            xT[rr + cc]       = xv.x; xT[rr + 64 + cc]  = xv.y;
            xT[rr + 128 + cc] = xv.z; xT[rr + 192 + cc] = xv.w;
            wT[rr + cc]       = wv.x; wT[rr + 64 + cc]  = wv.y;
            wT[rr + 128 + cc] = wv.z; wT[rr + 192 + cc] = wv.w;
        }
        __syncthreads();
        #pragma unroll 4
        for (int kk = 0; kk < 32; kk++) {
            int kg = kk >> 2;
            ulonglong2 A = *(const ulonglong2*)(xT + kk * 64 + ((ty ^ kg) << 2));
            float4 bw    = *(const float4*)   (wT + kk * 64 + ((tx ^ kg) << 2));
            u64 b0 = pk2(bw.x, bw.x), b1 = pk2(bw.y, bw.y);
            u64 b2 = pk2(bw.z, bw.z), b3 = pk2(bw.w, bw.w);
            fma2(acc2[0][0], A.x, b0); fma2(acc2[0][1], A.x, b1);
            fma2(acc2[0][2], A.x, b2); fma2(acc2[0][3], A.x, b3);
            fma2(acc2[1][0], A.y, b0); fma2(acc2[1][1], A.y, b1);
            fma2(acc2[1][2], A.y, b2); fma2(acc2[1][3], A.y, b3);
        }
    }

    if (transposed) {
        // out[b][d][t]: float4 along t
        const int b_  = row0 / TT;
        const int t0  = (row0 % TT) + 4 * ty;
        float* outT = out + (size_t)b_ * DHH * TT;
        #pragma unroll
        for (int j = 0; j < 4; j++) {
            const int d = 4 * tx + j;
            const float bj = bias[d];
            float2 f0 = up2(acc2[0][j]), f1 = up2(acc2[1][j]);
            *(float4*)(outT + (size_t)d * TT + t0) =
                make_float4(f0.x + bj, f0.y + bj, f1.x + bj, f1.y + bj);
        }
    } else {
        const float4 b4 = *(const float4*)(bias + 4 * tx);
        #pragma unroll
        for (int i2 = 0; i2 < 2; i2++) {
            float2 f0 = up2(acc2[i2][0]), f1 = up2(acc2[i2][1]);
            float2 f2 = up2(acc2[i2][2]), f3 = up2(acc2[i2][3]);
            int r0 = row0 + 4 * ty + 2 * i2;
            *(float4*)(out + (size_t)r0 * DHH + 4 * tx) =
                make_float4(f0.x + b4.x, f1.x + b4.y, f2.x + b4.z, f3.x + b4.w);
            *(float4*)(out + (size_t)(r0 + 1) * DHH + 4 * tx) =
                make_float4(f0.y + b4.x, f1.y + b4.y, f2.y + b4.z, f3.y + b4.w);
        }
    }
}

// ---------------------------------------------------------------------------
// Split-K causal flash attention. No max-tracking (|S| < ~50, raw exp safe).
// BLOCK_M=128, BLOCK_N=64, 256 threads, 8x4/thread FFMA2.
// Q,K read from transposed layout via cp.async; kT double-buffered prefetch;
// 3 syncthreads per k-tile.
// ---------------------------------------------------------------------------
__global__ __launch_bounds__(256, 2) void attn_kernel()
{
    const int b = blockIdx.y;
    int xx = blockIdx.x, qi = 0, split = 0;
    for (int q = NQT - 1; q >= 0; q--) {
        int ns = (2 * q + 2 + KCHUNK - 1) / KCHUNK;
        if (xx < ns) { qi = q; split = xx; break; }
        xx -= ns;
    }
    const int nkt = 2 * qi + 2;
    const int kt0 = split * KCHUNK;
    const int kt1 = min(kt0 + KCHUNK, nkt);
    const int q0 = qi * QTILE;

    const float* QT = g_Q + (size_t)b * DHH * TT;   // [d][t]
    const float* KT = g_K + (size_t)b * DHH * TT;   // [d][t]
    const float* V  = g_V + (size_t)b * TT * DHH;   // [t][d]

    extern __shared__ float sm[];
    float* qT = sm;                      // [d=64][r=128] swizzled  32KB
    float* kb0 = sm + 8192;              // 2 x [d=64][c=64]        32KB
    float* kb1 = kb0 + 4096;
    float* vs = kb1 + 4096;              // [c=64][d=64]            16KB
    float* pT = vs + 4096;               // [c=64][r=128] swizzled  32KB

    const int tid = threadIdx.x;
    const int tx = tid & 15, ty = tid >> 4;
    const unsigned sb = (unsigned)__cvta_generic_to_shared(sm);
    const unsigned qT_s = sb, kb0_s = sb + 8192 * 4, kb1_s = kb0_s + 4096 * 4;
    const unsigned vs_s = kb1_s + 4096 * 4;

    // ---- async tile loaders (direct copies, swizzled destinations) ----
    auto loadQ = [&]() {
        #pragma unroll
        for (int p = 0; p < 8; p++) {
            int idx = tid + p * 256;              // 64 d x 32 float4
            int d = idx >> 5, tq = idx & 31;
            unsigned dst = qT_s + (d * 128 + (((tq ^ (d >> 2)) & 31) << 2)) * 4;
            cpa16(dst, QT + (size_t)d * TT + q0 + 4 * tq);
        }
    };
    auto loadK = [&](int kt, unsigned kb_s) {
        const int k0 = kt * KTW;
        #pragma unroll
        for (int p = 0; p < 4; p++) {
            int idx = tid + p * 256;              // 64 d x 16 float4
            int d = idx >> 4, cq = idx & 15;
            unsigned dst = kb_s + (d * 64 + (((cq ^ (d >> 2)) & 15) << 2)) * 4;
            cpa16(dst, KT + (size_t)d * TT + k0 + 4 * cq);
        }
    };
    auto loadV = [&](int kt) {
        const int k0 = kt * KTW;
        #pragma unroll
        for (int p = 0; p < 4; p++) {
            int idx = tid + p * 256;              // 64 c x 16 float4
            int c = idx >> 4, dq = idx & 15;
            unsigned dst = vs_s + (c * 64 + (((dq ^ (c >> 2)) & 15) << 2)) * 4;
            cpa16(dst, V + (size_t)(k0 + c) * DHH + 4 * dq);
        }
    };

    loadQ(); loadK(kt0, kb0_s); loadV(kt0);
    cpa_commit();                                  // group 0

    u64 o2[4][4];
    #pragma unroll
    for (int i = 0; i < 4; i++)
        #pragma unroll
        for (int j = 0; j < 4; j++) o2[i][j] = 0ull;
    float lpart[8];
    #pragma unroll
    for (int i = 0; i < 8; i++) lpart[i] = 0.0f;

    for (int kt = kt0; kt < kt1; kt++) {
        const int k0 = kt * KTW;
        const int cur = (kt - kt0) & 1;
        const bool more = (kt + 1 < kt1);

        __syncthreads();                           // prior PV done: vs, pT, alt-kb free
        if (more) loadK(kt + 1, cur ? kb0_s : kb1_s);
        if (kt > kt0) loadV(kt);
        cpa_commit();
        cpa_wait<1>();                             // all but newest -> K(kt) (+Q,V first iter) ready
        __syncthreads();                           // smem visibility

        const float* kbuf = cur ? kb1 : kb0;

        // S = Q K^T
        u64 s2[4][4];
        #pragma unroll
        for (int i = 0; i < 4; i++)
            #pragma unroll
            for (int j = 0; j < 4; j++) s2[i][j] = 0ull;

        #pragma unroll 4
        for (int dg = 0; dg < 16; dg++) {
            const float* qb = qT + 4 * dg * 128;
            const float* kbp = kbuf + 4 * dg * 64;
            const int o0 = ((2 * ty) ^ dg) << 2;
            const int o1 = ((2 * ty + 1) ^ dg) << 2;
            const int ob = (tx ^ dg) << 2;
            #pragma unroll
            for (int e = 0; e < 4; e++) {
                ulonglong2 A0 = *(const ulonglong2*)(qb + e * 128 + o0);
                ulonglong2 A1 = *(const ulonglong2*)(qb + e * 128 + o1);
                float4 bk = *(const float4*)(kbp + e * 64 + ob);
                u64 b0 = pk2(bk.x, bk.x), b1 = pk2(bk.y, bk.y);
                u64 b2 = pk2(bk.z, bk.z), b3 = pk2(bk.w, bk.w);
                fma2(s2[0][0], A0.x, b0); fma2(s2[0][1], A0.x, b1);
                fma2(s2[0][2], A0.x, b2); fma2(s2[0][3], A0.x, b3);
                fma2(s2[1][0], A0.y, b0); fma2(s2[1][1], A0.y, b1);
                fma2(s2[1][2], A0.y, b2); fma2(s2[1][3], A0.y, b3);
                fma2(s2[2][0], A1.x, b0); fma2(s2[2][1], A1.x, b1);
                fma2(s2[2][2], A1.x, b2); fma2(s2[2][3], A1.x, b3);
                fma2(s2[3][0], A1.y, b0); fma2(s2[3][1], A1.y, b1);
                fma2(s2[3][2], A1.y, b2); fma2(s2[3][3], A1.y, b3);
            }
        }

        // unpack, mask (diagonal only), exp, row sums
        float p[8][4];
        #pragma unroll
        for (int i2 = 0; i2 < 4; i2++)
            #pragma unroll
            for (int j = 0; j < 4; j++) {
                float2 f = up2(s2[i2][j]);
                p[2 * i2][j] = f.x; p[2 * i2 + 1][j] = f.y;
            }
        if (kt >= 2 * qi) {
            #pragma unroll
            for (int i = 0; i < 8; i++)
                #pragma unroll
                for (int j = 0; j < 4; j++)
                    if (k0 + 4 * tx + j > q0 + 8 * ty + i) p[i][j] = -1e30f;
        }
        #pragma unroll
        for (int i = 0; i < 8; i++) {
            #pragma unroll
            for (int j = 0; j < 4; j++) p[i][j] = __expf(p[i][j]);
            lpart[i] += (p[i][0] + p[i][1]) + (p[i][2] + p[i][3]);
        }

        // pT free since loop-start sync (prior PV complete)
        #pragma unroll
        for (int j = 0; j < 4; j++) {
            int c = 4 * tx + j;
            float* pb = pT + c * 128;
            *(float4*)(pb + (((2 * ty) ^ tx) << 2))     = make_float4(p[0][j], p[1][j], p[2][j], p[3][j]);
            *(float4*)(pb + (((2 * ty + 1) ^ tx) << 2)) = make_float4(p[4][j], p[5][j], p[6][j], p[7][j]);
        }

        cpa_wait<0>();                             // V(kt) ready (K(kt+1) ~done too)
        __syncthreads();                           // pT + vs visible

        // O += P V
        #pragma unroll 4
        for (int cg = 0; cg < 16; cg++) {
            const float* pb = pT + 4 * cg * 128;
            const float* vb = vs + 4 * cg * 64;
            const int o0 = ((2 * ty) ^ cg) << 2;
            const int o1 = ((2 * ty + 1) ^ cg) << 2;
            const int ob = (tx ^ cg) << 2;
            #pragma unroll
            for (int e = 0; e < 4; e++) {
                ulonglong2 A0 = *(const ulonglong2*)(pb + e * 128 + o0);
                ulonglong2 A1 = *(const ulonglong2*)(pb + e * 128 + o1);
                float4 vv = *(const float4*)(vb + e * 64 + ob);
                u64 b0 = pk2(vv.x, vv.x), b1 = pk2(vv.y, vv.y);
                u64 b2 = pk2(vv.z, vv.z), b3 = pk2(vv.w, vv.w);
                fma2(o2[0][0], A0.x, b0); fma2(o2[0][1], A0.x, b1);
                fma2(o2[0][2], A0.x, b2); fma2(o2[0][3], A0.x, b3);
                fma2(o2[1][0], A0.y, b0); fma2(o2[1][1], A0.y, b1);
                fma2(o2[1][2], A0.y, b2); fma2(o2[1][3], A0.y, b3);
                fma2(o2[2][0], A1.x, b0); fma2(o2[2][1], A1.x, b1);
                fma2(o2[2][2], A1.x, b2); fma2(o2[2][3], A1.x, b3);
                fma2(o2[3][0], A1.y, b0); fma2(o2[3][1], A1.y, b1);
                fma2(o2[3][2], A1.y, b2); fma2(o2[3][3], A1.y, b3);
            }
        }
    }

    #pragma unroll
    for (int i = 0; i < 8; i++) {
        #pragma unroll
        for (int o = 1; o < 16; o <<= 1)
            lpart[i] += __shfl_xor_sync(0xffffffffu, lpart[i], o);
    }

    const size_t ubase = (size_t)(b * NQT + qi) * MAXSPLIT + split;
    float* Op = g_Op + ubase * (QTILE * DHH);
    #pragma unroll
    for (int i2 = 0; i2 < 4; i2++) {
        float2 f0 = up2(o2[i2][0]), f1 = up2(o2[i2][1]);
        float2 f2 = up2(o2[i2][2]), f3 = up2(o2[i2][3]);
        int r0 = 8 * ty + 2 * i2;
        *(float4*)(Op + (size_t)r0 * DHH + 4 * tx)       = make_float4(f0.x, f1.x, f2.x, f3.x);
        *(float4*)(Op + (size_t)(r0 + 1) * DHH + 4 * tx) = make_float4(f0.y, f1.y, f2.y, f3.y);
    }
    if (tx == 0) {
        #pragma unroll
        for (int i = 0; i < 8; i++)
            g_L[ubase * QTILE + 8 * ty + i] = lpart[i];
    }
}

// ---------------------------------------------------------------------------
// Combine partials: out = 8 * sum_s O_s / sum_s l_s
// ---------------------------------------------------------------------------
__global__ __launch_bounds__(256) void combine_kernel(float* __restrict__ out)
{
    const int qi = blockIdx.x, b = blockIdx.y;
    const int ns = (2 * qi + 2 + KCHUNK - 1) / KCHUNK;
    const int tid = threadIdx.x;
    const int r = tid >> 1;
    const int c0 = (tid & 1) * 32;
    const size_t tbase = (size_t)(b * NQT + qi) * MAXSPLIT;

    float acc[32];
    #pragma unroll
    for (int k = 0; k < 32; k++) acc[k] = 0.0f;
    float l = 0.0f;

    for (int s = 0; s < ns; s++) {
        const float* Op = g_Op + (tbase + s) * (size_t)(QTILE * DHH) + (size_t)r * DHH + c0;
        l += g_L[(tbase + s) * QTILE + r];
        #pragma unroll
        for (int j4 = 0; j4 < 8; j4++) {
            float4 v = *(const float4*)(Op + 4 * j4);
            acc[4 * j4 + 0] += v.x; acc[4 * j4 + 1] += v.y;
            acc[4 * j4 + 2] += v.z; acc[4 * j4 + 3] += v.w;
        }
    }

    const float inv = 8.0f / l;
    float* o = out + ((size_t)b * TT + (size_t)qi * QTILE + r) * DHH + c0;
    #pragma unroll
    for (int j4 = 0; j4 < 8; j4++)
        *(float4*)(o + 4 * j4) = make_float4(acc[4 * j4] * inv, acc[4 * j4 + 1] * inv,
                                             acc[4 * j4 + 2] * inv, acc[4 * j4 + 3] * inv);
}

// ---------------------------------------------------------------------------
extern "C" void kernel_launch(void* const* d_in, const int* in_sizes, int n_in,
                              void* d_out, int out_size)
{
    (void)in_sizes; (void)n_in; (void)out_size;
    const float* x  = (const float*)d_in[0];
    const float* Wq = (const float*)d_in[1];
    const float* bq = (const float*)d_in[2];
    const float* Wk = (const float*)d_in[3];
    const float* bk = (const float*)d_in[4];
    const float* Wv = (const float*)d_in[5];
    const float* bv = (const float*)d_in[6];
    float* out = (float*)d_out;

    qkv_kernel<<<dim3(BB * TT / 64, 3), 256>>>(x, Wq, bq, Wk, bk, Wv, bv);

    const int smem = (8192 + 2 * 4096 + 4096 + 8192) * (int)sizeof(float); // 112KB
    cudaFuncSetAttribute(attn_kernel, cudaFuncAttributeMaxDynamicSharedMemorySize, smem);
    attn_kernel<<<dim3(UNITS_PER_B, BB), 256, smem>>>();

    combine_kernel<<<dim3(NQT, BB), 256>>>(out);
}

// round 11
// speedup vs baseline: 1.6488x; 1.3029x over previous
#include <cuda_runtime.h>
#include <cuda_bf16.h>
#include <cstdint>

#define BB 4
#define TT 4096
#define CE 512
#define DHH 64
#define QTILE 128
#define NQT (TT / QTILE)          // 32
#define KTW 64
#define KCHUNK 4
#define MAXSPLIT 16
#define UNITS_PER_B 272

// tcgen05 availability: only on arch-specific ('a') compilation passes.
#if defined(__CUDA_ARCH_FEAT_SM103_ALL) || defined(__CUDA_ARCH_FEAT_SM100_ALL) || defined(__CUDA_ARCH_SPECIFIC__)
#define HAS_TC 1
#else
#define HAS_TC 0
#endif

typedef unsigned long long u64;

// ---------------- scratch (__device__ globals, allocation-free) ----------------
// Q, K stored TRANSPOSED per batch: [b][d][t]. V row-major [b][t][d].
__device__ float g_Q[BB * TT * DHH];
__device__ float g_K[BB * TT * DHH];
__device__ float g_V[BB * TT * DHH];
__device__ float g_Op[(size_t)BB * NQT * MAXSPLIT * QTILE * DHH];
__device__ float g_L[BB * NQT * MAXSPLIT * QTILE];
// bf16 split operands for tcgen05 QKV
__device__ __nv_bfloat16 g_xhi[BB * TT * CE];
__device__ __nv_bfloat16 g_xlo[BB * TT * CE];
__device__ __nv_bfloat16 g_Whi[3 * DHH * CE];
__device__ __nv_bfloat16 g_Wlo[3 * DHH * CE];

// ---------------- packed f32x2 helpers ----------------
__device__ __forceinline__ u64 pk2(float lo, float hi) {
    u64 r; asm("mov.b64 %0,{%1,%2};" : "=l"(r) : "f"(lo), "f"(hi)); return r;
}
__device__ __forceinline__ void fma2(u64& d, u64 a, u64 b) {
    asm("fma.rn.f32x2 %0,%1,%2,%0;" : "+l"(d) : "l"(a), "l"(b));
}
__device__ __forceinline__ float2 up2(u64 v) {
    float2 f; asm("mov.b64 {%0,%1},%2;" : "=f"(f.x), "=f"(f.y) : "l"(v)); return f;
}

// ---------------- cp.async helpers ----------------
__device__ __forceinline__ void cpa16(unsigned smem, const void* g) {
    asm volatile("cp.async.cg.shared.global [%0], [%1], 16;" :: "r"(smem), "l"(g));
}
__device__ __forceinline__ void cpa_commit() { asm volatile("cp.async.commit_group;"); }
template <int N> __device__ __forceinline__ void cpa_wait() {
    asm volatile("cp.async.wait_group %0;" :: "n"(N));
}

#define SWZ128(o) ((o) ^ (((o) >> 3) & 0x70))

#if HAS_TC
// ---------------- tcgen05 helpers (cg1) — compiled only on 'a' targets ----------------
__device__ __forceinline__ uint32_t elect_one() {
    uint32_t p;
    asm volatile("{\n\t.reg .pred p;\n\telect.sync _|p, 0xFFFFFFFF;\n\tselp.b32 %0,1,0,p;\n\t}" : "=r"(p));
    return p;
}
__device__ __forceinline__ u64 make_desc(uint32_t saddr) {
    // SW128, Blackwell version=1, LBO=1, SBO=64
    return ((u64)2 << 61) | ((u64)1 << 46) | ((u64)64 << 32) | ((u64)1 << 16)
         | (((u64)(saddr >> 4)) & 0x3FFF);
}
__device__ __forceinline__ void mma_f16_ss(uint32_t d, u64 ad, u64 bd, uint32_t idesc, bool en) {
    uint32_t e = en ? 1u : 0u;
    asm volatile(
        "{\n\t.reg .pred p;\n\tsetp.ne.u32 p, %5, 0;\n\t"
        "tcgen05.mma.cta_group::1.kind::f16 [%0], %1, %2, %3, {%4,%4,%4,%4}, p;\n\t}"
        :: "r"(d), "l"(ad), "l"(bd), "r"(idesc), "r"(0u), "r"(e) : "memory");
}
#define TC_ALLOC(saddr, n)  asm volatile("tcgen05.alloc.cta_group::1.sync.aligned.shared::cta.b32 [%0], %1;" :: "r"(saddr), "r"(n) : "memory")
#define TC_DEALLOC(t, n)    asm volatile("tcgen05.dealloc.cta_group::1.sync.aligned.b32 %0, %1;" :: "r"(t), "r"(n))
#define TC_RELINQ()         asm volatile("tcgen05.relinquish_alloc_permit.cta_group::1.sync.aligned;")
#define TC_COMMIT(mb)       asm volatile("tcgen05.commit.cta_group::1.mbarrier::arrive::one.shared::cluster.b64 [%0];" :: "r"(mb) : "memory")
#define TC_WAIT_LD()        asm volatile("tcgen05.wait::ld.sync.aligned;" ::: "memory")
#define TC_FENCE_AFTER()    asm volatile("tcgen05.fence::after_thread_sync;" ::: "memory")
#define MBAR_INIT(mb, n)    asm volatile("mbarrier.init.shared.b64 [%0], %1;" :: "r"(mb), "r"(n) : "memory")
#define FENCE_PA()          asm volatile("fence.proxy.async.shared::cta;" ::: "memory")

#define MBAR_WAIT(mb, par) do {                                             \
    uint32_t _mb = (mb), _p = (par), _d;                                    \
    asm volatile("{\n\t.reg .pred p;\n\t"                                   \
        "mbarrier.try_wait.parity.acquire.cta.shared::cta.b64 p, [%1], %2;\n\t" \
        "selp.b32 %0,1,0,p;\n\t}" : "=r"(_d) : "r"(_mb), "r"(_p) : "memory"); \
    if (!_d) {                                                              \
        asm volatile("{\n\t.reg .pred P1;\n\t"                              \
            "WL_%=:\n\t"                                                    \
            "mbarrier.try_wait.parity.acquire.cta.shared::cta.b64 P1, [%0], %1, 0x989680;\n\t" \
            "@P1 bra.uni WD_%=;\n\tbra.uni WL_%=;\n\tWD_%=:\n\t}"           \
            :: "r"(_mb), "r"(_p) : "memory");                               \
    }                                                                       \
} while (0)

#define LDTM_X32(r, t)                                                      \
    asm volatile("tcgen05.ld.sync.aligned.32x32b.x32.b32 "                  \
        "{%0,%1,%2,%3,%4,%5,%6,%7,%8,%9,%10,%11,%12,%13,%14,%15,"           \
        "%16,%17,%18,%19,%20,%21,%22,%23,%24,%25,%26,%27,%28,%29,%30,%31}, [%32];" \
        : "=r"((r)[0]),"=r"((r)[1]),"=r"((r)[2]),"=r"((r)[3]),              \
          "=r"((r)[4]),"=r"((r)[5]),"=r"((r)[6]),"=r"((r)[7]),              \
          "=r"((r)[8]),"=r"((r)[9]),"=r"((r)[10]),"=r"((r)[11]),            \
          "=r"((r)[12]),"=r"((r)[13]),"=r"((r)[14]),"=r"((r)[15]),          \
          "=r"((r)[16]),"=r"((r)[17]),"=r"((r)[18]),"=r"((r)[19]),          \
          "=r"((r)[20]),"=r"((r)[21]),"=r"((r)[22]),"=r"((r)[23]),          \
          "=r"((r)[24]),"=r"((r)[25]),"=r"((r)[26]),"=r"((r)[27]),          \
          "=r"((r)[28]),"=r"((r)[29]),"=r"((r)[30]),"=r"((r)[31])           \
        : "r"(t))
#endif // HAS_TC

// ---------------------------------------------------------------------------
// Convert x -> bf16 hi/lo (grid-stride over float4)
// ---------------------------------------------------------------------------
__global__ __launch_bounds__(256) void convert_x_kernel(const float* __restrict__ x)
{
    const int n4 = BB * TT * CE / 4;
    __nv_bfloat162* hi2 = reinterpret_cast<__nv_bfloat162*>(g_xhi);
    __nv_bfloat162* lo2 = reinterpret_cast<__nv_bfloat162*>(g_xlo);
    for (int i = blockIdx.x * blockDim.x + threadIdx.x; i < n4; i += gridDim.x * blockDim.x) {
        float4 v = reinterpret_cast<const float4*>(x)[i];
        __nv_bfloat16 h0 = __float2bfloat16_rn(v.x), h1 = __float2bfloat16_rn(v.y);
        __nv_bfloat16 h2 = __float2bfloat16_rn(v.z), h3 = __float2bfloat16_rn(v.w);
        __nv_bfloat16 l0 = __float2bfloat16_rn(v.x - __bfloat162float(h0));
        __nv_bfloat16 l1 = __float2bfloat16_rn(v.y - __bfloat162float(h1));
        __nv_bfloat16 l2 = __float2bfloat16_rn(v.z - __bfloat162float(h2));
        __nv_bfloat16 l3 = __float2bfloat16_rn(v.w - __bfloat162float(h3));
        hi2[2 * i]     = __nv_bfloat162(h0, h1);
        hi2[2 * i + 1] = __nv_bfloat162(h2, h3);
        lo2[2 * i]     = __nv_bfloat162(l0, l1);
        lo2[2 * i + 1] = __nv_bfloat162(l2, l3);
    }
}

__global__ __launch_bounds__(256) void convert_w_kernel(
    const float* __restrict__ Wq, const float* __restrict__ Wk, const float* __restrict__ Wv)
{
    const int per = DHH * CE;                  // 32768
    const int n = 3 * per;
    for (int i = blockIdx.x * blockDim.x + threadIdx.x; i < n; i += gridDim.x * blockDim.x) {
        int o = i / per, j = i - o * per;
        float v = (o == 0 ? Wq : (o == 1 ? Wk : Wv))[j];
        __nv_bfloat16 h = __float2bfloat16_rn(v);
        g_Whi[i] = h;
        g_Wlo[i] = __float2bfloat16_rn(v - __bfloat162float(h));
    }
}

// ---------------------------------------------------------------------------
// QKV kernel. On 'a' targets: tcgen05 3xBF16-split GEMM (one CTA: 128 rows,
// all 3 outputs, K=512 in 8 double-buffered chunks). On plain targets:
// correct SIMT fallback reading fp32 x/W directly.
// Epilogue (both paths): Q,K fp32 transposed [d][t]; V fp32 row-major; +bias.
// ---------------------------------------------------------------------------
#define BUFB 81920                 // bytes per pipeline buffer: A(2x16K) + B(6x8K)
#define OFF_ALO 16384
#define OFF_B   32768
#define OFF_CTRL (2 * BUFB)        // 163840: tmem ptr
#define OFF_MBAR (OFF_CTRL + 16)
#define QKV_SMEM (OFF_MBAR + 48)
#define QKV_IDESC 0x8100490u       // F32 accum, bf16 x bf16, N=64, M=128

__global__ __launch_bounds__(128) void qkv_tc_kernel(
    const float* __restrict__ x,
    const float* __restrict__ Wq, const float* __restrict__ Wk, const float* __restrict__ Wv,
    const float* __restrict__ bq, const float* __restrict__ bk, const float* __restrict__ bv)
{
#if HAS_TC
    extern __shared__ char smem[];
    const uint32_t sb = (uint32_t)__cvta_generic_to_shared(smem);
    const int tid = threadIdx.x, wid = tid >> 5, lid = tid & 31;
    const int row0 = blockIdx.x * 128;

    if (wid == 0) { TC_ALLOC(sb + OFF_CTRL, 256); }
    else          { TC_RELINQ(); }
    __syncthreads();
    uint32_t tmem;
    asm volatile("ld.shared.b32 %0, [%1];" : "=r"(tmem) : "r"(sb + OFF_CTRL));
    if (tid == 0) MBAR_INIT(sb + OFF_MBAR, 1);
    __syncthreads();

    auto loadChunk = [&](int c, int buf) {
        const uint32_t base = sb + buf * BUFB;
        const int c0 = c * 64;
        #pragma unroll
        for (int p = 0; p < 8; p++) {
            int idx = tid + p * 128;           // 1024: 128 rows x 8 chunks
            int r = idx >> 3, q = idx & 7;
            uint32_t off = r * 128 + q * 16;
            const size_t gsrc = (size_t)(row0 + r) * CE + c0 + q * 8;
            cpa16(base + SWZ128(off), g_xhi + gsrc);
            cpa16(base + OFF_ALO + SWZ128(off), g_xlo + gsrc);
        }
        #pragma unroll
        for (int p = 0; p < 24; p++) {
            int idx = tid + p * 128;           // 3072: 6 tiles x 64 rows x 8
            int t = idx >> 9, rem = idx & 511;
            int r = rem >> 3, q = rem & 7;
            uint32_t off = r * 128 + q * 16;
            const __nv_bfloat16* src = (t < 3 ? g_Whi : g_Wlo)
                + (size_t)((t % 3) * DHH + r) * CE + c0 + q * 8;
            cpa16(base + OFF_B + t * 8192 + SWZ128(off), src);
        }
    };

    loadChunk(0, 0);
    cpa_commit();

    for (int c = 0; c < 8; c++) {
        const int buf = c & 1;
        cpa_wait<0>();
        __syncthreads();
        FENCE_PA();
        if (c < 7) { loadChunk(c + 1, 1 - buf); cpa_commit(); }

        if (wid == 0 && elect_one()) {
            const uint32_t base = sb + buf * BUFB;
            const u64 ad_hi = make_desc(base);
            const u64 ad_lo = make_desc(base + OFF_ALO);
            #pragma unroll
            for (int o = 0; o < 3; o++) {
                const uint32_t dT = tmem + o * 64;
                #pragma unroll
                for (int pair = 0; pair < 3; pair++) {
                    const u64 ad = (pair == 2) ? ad_lo : ad_hi;
                    const int hl = (pair == 1) ? 1 : 0;
                    const u64 bd = make_desc(base + OFF_B + (hl * 3 + o) * 8192);
                    #pragma unroll
                    for (int k = 0; k < 4; k++)
                        mma_f16_ss(dT, ad + 2 * k, bd + 2 * k, QKV_IDESC,
                                   !(c == 0 && pair == 0 && k == 0));
                }
            }
            TC_COMMIT(sb + OFF_MBAR);
        }
        MBAR_WAIT(sb + OFF_MBAR, c & 1);
    }
    TC_FENCE_AFTER();

    // epilogue: warp w handles rows w*32+lid (TMEM subpartition = warp)
    const int r = wid * 32 + lid;
    const int grow = row0 + r;
    const int b_ = grow >> 12;
    const int t  = grow & (TT - 1);

    uint32_t dr[64];
    #pragma unroll
    for (int o = 0; o < 3; o++) {
        LDTM_X32(dr,      tmem + o * 64);
        LDTM_X32(dr + 32, tmem + o * 64 + 32);
        TC_WAIT_LD();
        const float* bias = (o == 0 ? bq : (o == 1 ? bk : bv));
        if (o < 2) {
            float* outT = (o == 0 ? g_Q : g_K) + (size_t)b_ * DHH * TT;
            #pragma unroll
            for (int d = 0; d < 64; d++)
                outT[(size_t)d * TT + t] = __uint_as_float(dr[d]) + bias[d];
        } else {
            float* ov = g_V + (size_t)grow * DHH;
            #pragma unroll
            for (int d4 = 0; d4 < 16; d4++) {
                float4 w = make_float4(__uint_as_float(dr[4 * d4 + 0]) + bias[4 * d4 + 0],
                                       __uint_as_float(dr[4 * d4 + 1]) + bias[4 * d4 + 1],
                                       __uint_as_float(dr[4 * d4 + 2]) + bias[4 * d4 + 2],
                                       __uint_as_float(dr[4 * d4 + 3]) + bias[4 * d4 + 3]);
                *(float4*)(ov + 4 * d4) = w;
            }
        }
    }

    __syncthreads();
    if (wid == 0) TC_DEALLOC(tmem, 256);
#else
    // ---- SIMT fallback (correct on any target; used only if the runtime
    // selects a non-'a' compilation pass) ----
    const int tid = threadIdx.x;
    const int grow = blockIdx.x * 128 + tid;      // one row per thread
    const int b_ = grow >> 12;
    const int t  = grow & (TT - 1);
    const float4* xr = (const float4*)(x + (size_t)grow * CE);

    #pragma unroll
    for (int o = 0; o < 3; o++) {
        const float* W    = (o == 0 ? Wq : (o == 1 ? Wk : Wv));
        const float* bias = (o == 0 ? bq : (o == 1 ? bk : bv));
        for (int d = 0; d < DHH; d++) {
            const float4* wr = (const float4*)(W + (size_t)d * CE);
            float acc = 0.0f;
            #pragma unroll 8
            for (int c = 0; c < CE / 4; c++) {
                float4 a = xr[c], w = wr[c];
                acc += a.x * w.x + a.y * w.y + a.z * w.z + a.w * w.w;
            }
            acc += bias[d];
            if (o < 2) {
                float* outT = (o == 0 ? g_Q : g_K) + (size_t)b_ * DHH * TT;
                outT[(size_t)d * TT + t] = acc;
            } else {
                g_V[(size_t)grow * DHH + d] = acc;
            }
        }
    }
#endif
}

// ---------------------------------------------------------------------------
// Split-K causal flash attention (round-6 winner, unchanged).
// ---------------------------------------------------------------------------
__global__ __launch_bounds__(256, 2) void attn_kernel()
{
    const int b = blockIdx.y;
    int xx = blockIdx.x, qi = 0, split = 0;
    for (int q = NQT - 1; q >= 0; q--) {
        int ns = (2 * q + 2 + KCHUNK - 1) / KCHUNK;
        if (xx < ns) { qi = q; split = xx; break; }
        xx -= ns;
    }
    const int nkt = 2 * qi + 2;
    const int kt0 = split * KCHUNK;
    const int kt1 = min(kt0 + KCHUNK, nkt);
    const int q0 = qi * QTILE;

    const float* QT = g_Q + (size_t)b * DHH * TT;
    const float* KT = g_K + (size_t)b * DHH * TT;
    const float* V  = g_V + (size_t)b * TT * DHH;

    extern __shared__ float sm[];
    float* qT = sm;
    float* kb0 = sm + 8192;
    float* kb1 = kb0 + 4096;
    float* vs = kb1 + 4096;
    float* pT = vs + 4096;

    const int tid = threadIdx.x;
    const int tx = tid & 15, ty = tid >> 4;
    const unsigned sb = (unsigned)__cvta_generic_to_shared(sm);
    const unsigned qT_s = sb, kb0_s = sb + 8192 * 4, kb1_s = kb0_s + 4096 * 4;
    const unsigned vs_s = kb1_s + 4096 * 4;

    auto loadQ = [&]() {
        #pragma unroll
        for (int p = 0; p < 8; p++) {
            int idx = tid + p * 256;
            int d = idx >> 5, tq = idx & 31;
            unsigned dst = qT_s + (d * 128 + (((tq ^ (d >> 2)) & 31) << 2)) * 4;
            cpa16(dst, QT + (size_t)d * TT + q0 + 4 * tq);
        }
    };
    auto loadK = [&](int kt, unsigned kb_s) {
        const int k0 = kt * KTW;
        #pragma unroll
        for (int p = 0; p < 4; p++) {
            int idx = tid + p * 256;
            int d = idx >> 4, cq = idx & 15;
            unsigned dst = kb_s + (d * 64 + (((cq ^ (d >> 2)) & 15) << 2)) * 4;
            cpa16(dst, KT + (size_t)d * TT + k0 + 4 * cq);
        }
    };
    auto loadV = [&](int kt) {
        const int k0 = kt * KTW;
        #pragma unroll
        for (int p = 0; p < 4; p++) {
            int idx = tid + p * 256;
            int c = idx >> 4, dq = idx & 15;
            unsigned dst = vs_s + (c * 64 + (((dq ^ (c >> 2)) & 15) << 2)) * 4;
            cpa16(dst, V + (size_t)(k0 + c) * DHH + 4 * dq);
        }
    };

    loadQ(); loadK(kt0, kb0_s); loadV(kt0);
    cpa_commit();

    u64 o2[4][4];
    #pragma unroll
    for (int i = 0; i < 4; i++)
        #pragma unroll
        for (int j = 0; j < 4; j++) o2[i][j] = 0ull;
    float lpart[8];
    #pragma unroll
    for (int i = 0; i < 8; i++) lpart[i] = 0.0f;

    for (int kt = kt0; kt < kt1; kt++) {
        const int k0 = kt * KTW;
        const int cur = (kt - kt0) & 1;
        const bool more = (kt + 1 < kt1);

        __syncthreads();
        if (more) loadK(kt + 1, cur ? kb0_s : kb1_s);
        if (kt > kt0) loadV(kt);
        cpa_commit();
        cpa_wait<1>();
        __syncthreads();

        const float* kbuf = cur ? kb1 : kb0;

        u64 s2[4][4];
        #pragma unroll
        for (int i = 0; i < 4; i++)
            #pragma unroll
            for (int j = 0; j < 4; j++) s2[i][j] = 0ull;

        #pragma unroll 4
        for (int dg = 0; dg < 16; dg++) {
            const float* qb = qT + 4 * dg * 128;
            const float* kbp = kbuf + 4 * dg * 64;
            const int o0 = ((2 * ty) ^ dg) << 2;
            const int o1 = ((2 * ty + 1) ^ dg) << 2;
            const int ob = (tx ^ dg) << 2;
            #pragma unroll
            for (int e = 0; e < 4; e++) {
                ulonglong2 A0 = *(const ulonglong2*)(qb + e * 128 + o0);
                ulonglong2 A1 = *(const ulonglong2*)(qb + e * 128 + o1);
                float4 bk = *(const float4*)(kbp + e * 64 + ob);
                u64 b0 = pk2(bk.x, bk.x), b1 = pk2(bk.y, bk.y);
                u64 b2 = pk2(bk.z, bk.z), b3 = pk2(bk.w, bk.w);
                fma2(s2[0][0], A0.x, b0); fma2(s2[0][1], A0.x, b1);
                fma2(s2[0][2], A0.x, b2); fma2(s2[0][3], A0.x, b3);
                fma2(s2[1][0], A0.y, b0); fma2(s2[1][1], A0.y, b1);
                fma2(s2[1][2], A0.y, b2); fma2(s2[1][3], A0.y, b3);
                fma2(s2[2][0], A1.x, b0); fma2(s2[2][1], A1.x, b1);
                fma2(s2[2][2], A1.x, b2); fma2(s2[2][3], A1.x, b3);
                fma2(s2[3][0], A1.y, b0); fma2(s2[3][1], A1.y, b1);
                fma2(s2[3][2], A1.y, b2); fma2(s2[3][3], A1.y, b3);
            }
        }

        float p[8][4];
        #pragma unroll
        for (int i2 = 0; i2 < 4; i2++)
            #pragma unroll
            for (int j = 0; j < 4; j++) {
                float2 f = up2(s2[i2][j]);
                p[2 * i2][j] = f.x; p[2 * i2 + 1][j] = f.y;
            }
        if (kt >= 2 * qi) {
            #pragma unroll
            for (int i = 0; i < 8; i++)
                #pragma unroll
                for (int j = 0; j < 4; j++)
                    if (k0 + 4 * tx + j > q0 + 8 * ty + i) p[i][j] = -1e30f;
        }
        #pragma unroll
        for (int i = 0; i < 8; i++) {
            #pragma unroll
            for (int j = 0; j < 4; j++) p[i][j] = __expf(p[i][j]);
            lpart[i] += (p[i][0] + p[i][1]) + (p[i][2] + p[i][3]);
        }

        #pragma unroll
        for (int j = 0; j < 4; j++) {
            int c = 4 * tx + j;
            float* pb = pT + c * 128;
            *(float4*)(pb + (((2 * ty) ^ tx) << 2))     = make_float4(p[0][j], p[1][j], p[2][j], p[3][j]);
            *(float4*)(pb + (((2 * ty + 1) ^ tx) << 2)) = make_float4(p[4][j], p[5][j], p[6][j], p[7][j]);
        }

        cpa_wait<0>();
        __syncthreads();

        #pragma unroll 4
        for (int cg = 0; cg < 16; cg++) {
            const float* pb = pT + 4 * cg * 128;
            const float* vb = vs + 4 * cg * 64;
            const int o0 = ((2 * ty) ^ cg) << 2;
            const int o1 = ((2 * ty + 1) ^ cg) << 2;
            const int ob = (tx ^ cg) << 2;
            #pragma unroll
            for (int e = 0; e < 4; e++) {
                ulonglong2 A0 = *(const ulonglong2*)(pb + e * 128 + o0);
                ulonglong2 A1 = *(const ulonglong2*)(pb + e * 128 + o1);
                float4 vv = *(const float4*)(vb + e * 64 + ob);
                u64 b0 = pk2(vv.x, vv.x), b1 = pk2(vv.y, vv.y);
                u64 b2 = pk2(vv.z, vv.z), b3 = pk2(vv.w, vv.w);
                fma2(o2[0][0], A0.x, b0); fma2(o2[0][1], A0.x, b1);
                fma2(o2[0][2], A0.x, b2); fma2(o2[0][3], A0.x, b3);
                fma2(o2[1][0], A0.y, b0); fma2(o2[1][1], A0.y, b1);
                fma2(o2[1][2], A0.y, b2); fma2(o2[1][3], A0.y, b3);
                fma2(o2[2][0], A1.x, b0); fma2(o2[2][1], A1.x, b1);
                fma2(o2[2][2], A1.x, b2); fma2(o2[2][3], A1.x, b3);
                fma2(o2[3][0], A1.y, b0); fma2(o2[3][1], A1.y, b1);
                fma2(o2[3][2], A1.y, b2); fma2(o2[3][3], A1.y, b3);
            }
        }
    }

    #pragma unroll
    for (int i = 0; i < 8; i++) {
        #pragma unroll
        for (int o = 1; o < 16; o <<= 1)
            lpart[i] += __shfl_xor_sync(0xffffffffu, lpart[i], o);
    }

    const size_t ubase = (size_t)(b * NQT + qi) * MAXSPLIT + split;
    float* Op = g_Op + ubase * (QTILE * DHH);
    #pragma unroll
    for (int i2 = 0; i2 < 4; i2++) {
        float2 f0 = up2(o2[i2][0]), f1 = up2(o2[i2][1]);
        float2 f2 = up2(o2[i2][2]), f3 = up2(o2[i2][3]);
        int r0 = 8 * ty + 2 * i2;
        *(float4*)(Op + (size_t)r0 * DHH + 4 * tx)       = make_float4(f0.x, f1.x, f2.x, f3.x);
        *(float4*)(Op + (size_t)(r0 + 1) * DHH + 4 * tx) = make_float4(f0.y, f1.y, f2.y, f3.y);
    }
    if (tx == 0) {
        #pragma unroll
        for (int i = 0; i < 8; i++)
            g_L[ubase * QTILE + 8 * ty + i] = lpart[i];
    }
}

// ---------------------------------------------------------------------------
__global__ __launch_bounds__(256) void combine_kernel(float* __restrict__ out)
{
    const int qi = blockIdx.x, b = blockIdx.y;
    const int ns = (2 * qi + 2 + KCHUNK - 1) / KCHUNK;
    const int tid = threadIdx.x;
    const int r = tid >> 1;
    const int c0 = (tid & 1) * 32;
    const size_t tbase = (size_t)(b * NQT + qi) * MAXSPLIT;

    float acc[32];
    #pragma unroll
    for (int k = 0; k < 32; k++) acc[k] = 0.0f;
    float l = 0.0f;

    for (int s = 0; s < ns; s++) {
        const float* Op = g_Op + (tbase + s) * (size_t)(QTILE * DHH) + (size_t)r * DHH + c0;
        l += g_L[(tbase + s) * QTILE + r];
        #pragma unroll
        for (int j4 = 0; j4 < 8; j4++) {
            float4 v = *(const float4*)(Op + 4 * j4);
            acc[4 * j4 + 0] += v.x; acc[4 * j4 + 1] += v.y;
            acc[4 * j4 + 2] += v.z; acc[4 * j4 + 3] += v.w;
        }
    }

    const float inv = 8.0f / l;
    float* o = out + ((size_t)b * TT + (size_t)qi * QTILE + r) * DHH + c0;
    #pragma unroll
    for (int j4 = 0; j4 < 8; j4++)
        *(float4*)(o + 4 * j4) = make_float4(acc[4 * j4] * inv, acc[4 * j4 + 1] * inv,
                                             acc[4 * j4 + 2] * inv, acc[4 * j4 + 3] * inv);
}

// ---------------------------------------------------------------------------
extern "C" void kernel_launch(void* const* d_in, const int* in_sizes, int n_in,
                              void* d_out, int out_size)
{
    (void)in_sizes; (void)n_in; (void)out_size;
    const float* x  = (const float*)d_in[0];
    const float* Wq = (const float*)d_in[1];
    const float* bq = (const float*)d_in[2];
    const float* Wk = (const float*)d_in[3];
    const float* bk = (const float*)d_in[4];
    const float* Wv = (const float*)d_in[5];
    const float* bv = (const float*)d_in[6];
    float* out = (float*)d_out;

    convert_x_kernel<<<1024, 256>>>(x);
    convert_w_kernel<<<96, 256>>>(Wq, Wk, Wv);

    cudaFuncSetAttribute(qkv_tc_kernel, cudaFuncAttributeMaxDynamicSharedMemorySize, QKV_SMEM);
    qkv_tc_kernel<<<BB * TT / 128, 128, QKV_SMEM>>>(x, Wq, Wk, Wv, bq, bk, bv);

    const int smem = (8192 + 2 * 4096 + 4096 + 8192) * (int)sizeof(float);
    cudaFuncSetAttribute(attn_kernel, cudaFuncAttributeMaxDynamicSharedMemorySize, smem);
    attn_kernel<<<dim3(UNITS_PER_B, BB), 256, smem>>>();

    combine_kernel<<<dim3(NQT, BB), 256>>>(out);
}

// round 13
// speedup vs baseline: 2.9421x; 1.7844x over previous
#include <cuda_runtime.h>
#include <cuda_bf16.h>
#include <cstdint>

#define BB 4
#define TT 4096
#define CE 512
#define DHH 64
#define QTILE 128
#define NQT (TT / QTILE)          // 32
#define KTW 64
#define KCHUNK 4
#define MAXSPLIT 16
#define UNITS_PER_B 272

// tcgen05 availability: only on arch-specific ('a') compilation passes.
#if defined(__CUDA_ARCH_FEAT_SM103_ALL) || defined(__CUDA_ARCH_FEAT_SM100_ALL) || defined(__CUDA_ARCH_SPECIFIC__)
#define HAS_TC 1
#else
#define HAS_TC 0
#endif

typedef unsigned long long u64;

// ---------------- scratch (__device__ globals, allocation-free) ----------------
// bf16 split operands. Q,K: [b][t][d] row-major. V: [b][d][t] transposed.
__device__ __nv_bfloat16 g_Qhi[BB * TT * DHH];
__device__ __nv_bfloat16 g_Qlo[BB * TT * DHH];
__device__ __nv_bfloat16 g_Khi[BB * TT * DHH];
__device__ __nv_bfloat16 g_Klo[BB * TT * DHH];
__device__ __nv_bfloat16 g_Vhi[BB * TT * DHH];
__device__ __nv_bfloat16 g_Vlo[BB * TT * DHH];
__device__ float g_Op[(size_t)BB * NQT * MAXSPLIT * QTILE * DHH];
__device__ float g_L[BB * NQT * MAXSPLIT * QTILE];
// bf16 split inputs for QKV GEMM
__device__ __nv_bfloat16 g_xhi[BB * TT * CE];
__device__ __nv_bfloat16 g_xlo[BB * TT * CE];
__device__ __nv_bfloat16 g_Whi[3 * DHH * CE];
__device__ __nv_bfloat16 g_Wlo[3 * DHH * CE];

// ---------------- cp.async helpers ----------------
__device__ __forceinline__ void cpa16(unsigned smem, const void* g) {
    asm volatile("cp.async.cg.shared.global [%0], [%1], 16;" :: "r"(smem), "l"(g));
}
__device__ __forceinline__ void cpa_commit() { asm volatile("cp.async.commit_group;"); }
template <int N> __device__ __forceinline__ void cpa_wait() {
    asm volatile("cp.async.wait_group %0;" :: "n"(N));
}

#define SWZ128(o) ((o) ^ (((o) >> 3) & 0x70))

// split a fp32 into bf16 hi + residual lo, packed as u32 pairs
__device__ __forceinline__ void split2(float p0, float p1, uint32_t& hu, uint32_t& lu) {
    __nv_bfloat162 hh = __floats2bfloat162_rn(p0, p1);
    hu = *reinterpret_cast<uint32_t*>(&hh);
    float h0 = __uint_as_float(hu << 16);
    float h1 = __uint_as_float(hu & 0xffff0000u);
    __nv_bfloat162 ll = __floats2bfloat162_rn(p0 - h0, p1 - h1);
    lu = *reinterpret_cast<uint32_t*>(&ll);
}

#if HAS_TC
// ---------------- tcgen05 helpers (cg1) — 'a' targets only ----------------
__device__ __forceinline__ uint32_t elect_one() {
    uint32_t p;
    asm volatile("{\n\t.reg .pred p;\n\telect.sync _|p, 0xFFFFFFFF;\n\tselp.b32 %0,1,0,p;\n\t}" : "=r"(p));
    return p;
}
__device__ __forceinline__ u64 make_desc(uint32_t saddr) {
    return ((u64)2 << 61) | ((u64)1 << 46) | ((u64)64 << 32) | ((u64)1 << 16)
         | (((u64)(saddr >> 4)) & 0x3FFF);
}
__device__ __forceinline__ void mma_f16_ss(uint32_t d, u64 ad, u64 bd, uint32_t idesc, bool en) {
    uint32_t e = en ? 1u : 0u;
    asm volatile(
        "{\n\t.reg .pred p;\n\tsetp.ne.u32 p, %5, 0;\n\t"
        "tcgen05.mma.cta_group::1.kind::f16 [%0], %1, %2, %3, {%4,%4,%4,%4}, p;\n\t}"
        :: "r"(d), "l"(ad), "l"(bd), "r"(idesc), "r"(0u), "r"(e) : "memory");
}
#define TC_ALLOC(saddr, n)  asm volatile("tcgen05.alloc.cta_group::1.sync.aligned.shared::cta.b32 [%0], %1;" :: "r"(saddr), "r"(n) : "memory")
#define TC_DEALLOC(t, n)    asm volatile("tcgen05.dealloc.cta_group::1.sync.aligned.b32 %0, %1;" :: "r"(t), "r"(n))
#define TC_RELINQ()         asm volatile("tcgen05.relinquish_alloc_permit.cta_group::1.sync.aligned;")
#define TC_COMMIT(mb)       asm volatile("tcgen05.commit.cta_group::1.mbarrier::arrive::one.shared::cluster.b64 [%0];" :: "r"(mb) : "memory")
#define TC_WAIT_LD()        asm volatile("tcgen05.wait::ld.sync.aligned;" ::: "memory")
#define TC_FENCE_AFTER()    asm volatile("tcgen05.fence::after_thread_sync;" ::: "memory")
#define MBAR_INIT(mb, n)    asm volatile("mbarrier.init.shared.b64 [%0], %1;" :: "r"(mb), "r"(n) : "memory")
#define FENCE_PA()          asm volatile("fence.proxy.async.shared::cta;" ::: "memory")

#define MBAR_WAIT(mb, par) do {                                             \
    uint32_t _mb = (mb), _p = (uint32_t)(par), _d;                          \
    asm volatile("{\n\t.reg .pred p;\n\t"                                   \
        "mbarrier.try_wait.parity.acquire.cta.shared::cta.b64 p, [%1], %2;\n\t" \
        "selp.b32 %0,1,0,p;\n\t}" : "=r"(_d) : "r"(_mb), "r"(_p) : "memory"); \
    if (!_d) {                                                              \
        asm volatile("{\n\t.reg .pred P1;\n\t"                              \
            "WL_%=:\n\t"                                                    \
            "mbarrier.try_wait.parity.acquire.cta.shared::cta.b64 P1, [%0], %1, 0x989680;\n\t" \
            "@P1 bra.uni WD_%=;\n\tbra.uni WL_%=;\n\tWD_%=:\n\t}"           \
            :: "r"(_mb), "r"(_p) : "memory");                               \
    }                                                                       \
} while (0)

#define LDTM_X32(r, t)                                                      \
    asm volatile("tcgen05.ld.sync.aligned.32x32b.x32.b32 "                  \
        "{%0,%1,%2,%3,%4,%5,%6,%7,%8,%9,%10,%11,%12,%13,%14,%15,"           \
        "%16,%17,%18,%19,%20,%21,%22,%23,%24,%25,%26,%27,%28,%29,%30,%31}, [%32];" \
        : "=r"((r)[0]),"=r"((r)[1]),"=r"((r)[2]),"=r"((r)[3]),              \
          "=r"((r)[4]),"=r"((r)[5]),"=r"((r)[6]),"=r"((r)[7]),              \
          "=r"((r)[8]),"=r"((r)[9]),"=r"((r)[10]),"=r"((r)[11]),            \
          "=r"((r)[12]),"=r"((r)[13]),"=r"((r)[14]),"=r"((r)[15]),          \
          "=r"((r)[16]),"=r"((r)[17]),"=r"((r)[18]),"=r"((r)[19]),          \
          "=r"((r)[20]),"=r"((r)[21]),"=r"((r)[22]),"=r"((r)[23]),          \
          "=r"((r)[24]),"=r"((r)[25]),"=r"((r)[26]),"=r"((r)[27]),          \
          "=r"((r)[28]),"=r"((r)[29]),"=r"((r)[30]),"=r"((r)[31])           \
        : "r"(t))
#endif // HAS_TC

// ---------------------------------------------------------------------------
// Converters (x, W -> bf16 hi/lo)
// ---------------------------------------------------------------------------
__global__ __launch_bounds__(256) void convert_x_kernel(const float* __restrict__ x)
{
    const int n4 = BB * TT * CE / 4;
    __nv_bfloat162* hi2 = reinterpret_cast<__nv_bfloat162*>(g_xhi);
    __nv_bfloat162* lo2 = reinterpret_cast<__nv_bfloat162*>(g_xlo);
    for (int i = blockIdx.x * blockDim.x + threadIdx.x; i < n4; i += gridDim.x * blockDim.x) {
        float4 v = reinterpret_cast<const float4*>(x)[i];
        uint32_t h0, l0, h1, l1;
        split2(v.x, v.y, h0, l0);
        split2(v.z, v.w, h1, l1);
        hi2[2 * i]     = *reinterpret_cast<__nv_bfloat162*>(&h0);
        hi2[2 * i + 1] = *reinterpret_cast<__nv_bfloat162*>(&h1);
        lo2[2 * i]     = *reinterpret_cast<__nv_bfloat162*>(&l0);
        lo2[2 * i + 1] = *reinterpret_cast<__nv_bfloat162*>(&l1);
    }
}

__global__ __launch_bounds__(256) void convert_w_kernel(
    const float* __restrict__ Wq, const float* __restrict__ Wk, const float* __restrict__ Wv)
{
    const int per = DHH * CE;
    const int n = 3 * per;
    for (int i = blockIdx.x * blockDim.x + threadIdx.x; i < n; i += gridDim.x * blockDim.x) {
        int o = i / per, j = i - o * per;
        float v = (o == 0 ? Wq : (o == 1 ? Wk : Wv))[j];
        __nv_bfloat16 h = __float2bfloat16_rn(v);
        g_Whi[i] = h;
        g_Wlo[i] = __float2bfloat16_rn(v - __bfloat162float(h));
    }
}

// ---------------------------------------------------------------------------
// QKV via tcgen05 (3xBF16 split). Epilogue emits bf16 hi/lo attention operands:
// Q,K row-major [t][d]; V transposed [d][t].
// ---------------------------------------------------------------------------
#define BUFB 81920
#define OFF_ALO 16384
#define OFF_B   32768
#define OFF_CTRL (2 * BUFB)
#define OFF_MBAR (OFF_CTRL + 16)
#define QKV_SMEM (OFF_MBAR + 48)
#define IDESC_128x64 0x8100490u    // F32 accum, bf16 x bf16, N=64, M=128

__global__ __launch_bounds__(128) void qkv_tc_kernel(
    const float* __restrict__ x,
    const float* __restrict__ Wq, const float* __restrict__ Wk, const float* __restrict__ Wv,
    const float* __restrict__ bq, const float* __restrict__ bk, const float* __restrict__ bv)
{
#if HAS_TC
    extern __shared__ char smem[];
    const uint32_t sb = (uint32_t)__cvta_generic_to_shared(smem);
    const int tid = threadIdx.x, wid = tid >> 5, lid = tid & 31;
    const int row0 = blockIdx.x * 128;

    if (wid == 0) { TC_ALLOC(sb + OFF_CTRL, 256); }
    else          { TC_RELINQ(); }
    __syncthreads();
    uint32_t tmem;
    asm volatile("ld.shared.b32 %0, [%1];" : "=r"(tmem) : "r"(sb + OFF_CTRL));
    if (tid == 0) MBAR_INIT(sb + OFF_MBAR, 1);
    __syncthreads();

    auto loadChunk = [&](int c, int buf) {
        const uint32_t base = sb + buf * BUFB;
        const int c0 = c * 64;
        #pragma unroll
        for (int p = 0; p < 8; p++) {
            int idx = tid + p * 128;
            int r = idx >> 3, q = idx & 7;
            uint32_t off = r * 128 + q * 16;
            const size_t gsrc = (size_t)(row0 + r) * CE + c0 + q * 8;
            cpa16(base + SWZ128(off), g_xhi + gsrc);
            cpa16(base + OFF_ALO + SWZ128(off), g_xlo + gsrc);
        }
        #pragma unroll
        for (int p = 0; p < 24; p++) {
            int idx = tid + p * 128;
            int t = idx >> 9, rem = idx & 511;
            int r = rem >> 3, q = rem & 7;
            uint32_t off = r * 128 + q * 16;
            const __nv_bfloat16* src = (t < 3 ? g_Whi : g_Wlo)
                + (size_t)((t % 3) * DHH + r) * CE + c0 + q * 8;
            cpa16(base + OFF_B + t * 8192 + SWZ128(off), src);
        }
    };

    loadChunk(0, 0);
    cpa_commit();

    for (int c = 0; c < 8; c++) {
        const int buf = c & 1;
        cpa_wait<0>();
        __syncthreads();
        FENCE_PA();
        if (c < 7) { loadChunk(c + 1, 1 - buf); cpa_commit(); }

        if (wid == 0 && elect_one()) {
            const uint32_t base = sb + buf * BUFB;
            const u64 ad_hi = make_desc(base);
            const u64 ad_lo = make_desc(base + OFF_ALO);
            #pragma unroll
            for (int o = 0; o < 3; o++) {
                const uint32_t dT = tmem + o * 64;
                #pragma unroll
                for (int pair = 0; pair < 3; pair++) {
                    const u64 ad = (pair == 2) ? ad_lo : ad_hi;
                    const int hl = (pair == 1) ? 1 : 0;
                    const u64 bd = make_desc(base + OFF_B + (hl * 3 + o) * 8192);
                    #pragma unroll
                    for (int k = 0; k < 4; k++)
                        mma_f16_ss(dT, ad + 2 * k, bd + 2 * k, IDESC_128x64,
                                   !(c == 0 && pair == 0 && k == 0));
                }
            }
            TC_COMMIT(sb + OFF_MBAR);
        }
        MBAR_WAIT(sb + OFF_MBAR, c & 1);
    }
    TC_FENCE_AFTER();

    // epilogue: warp w rows 32w+lid; emit bf16 hi/lo
    const int r = wid * 32 + lid;
    const int grow = row0 + r;
    const int b_ = grow >> 12;
    const int t  = grow & (TT - 1);

    uint32_t dr[64];
    #pragma unroll
    for (int o = 0; o < 3; o++) {
        LDTM_X32(dr,      tmem + o * 64);
        LDTM_X32(dr + 32, tmem + o * 64 + 32);
        TC_WAIT_LD();
        const float* bias = (o == 0 ? bq : (o == 1 ? bk : bv));
        float v[64];
        #pragma unroll
        for (int d = 0; d < 64; d++) v[d] = __uint_as_float(dr[d]) + bias[d];

        if (o < 2) {
            uint32_t hu[32], lu[32];
            #pragma unroll
            for (int j2 = 0; j2 < 32; j2++) split2(v[2 * j2], v[2 * j2 + 1], hu[j2], lu[j2]);
            uint4* H = (uint4*)((o == 0 ? g_Qhi : g_Khi) + (size_t)grow * DHH);
            uint4* L = (uint4*)((o == 0 ? g_Qlo : g_Klo) + (size_t)grow * DHH);
            #pragma unroll
            for (int i = 0; i < 8; i++) {
                H[i] = make_uint4(hu[4 * i], hu[4 * i + 1], hu[4 * i + 2], hu[4 * i + 3]);
                L[i] = make_uint4(lu[4 * i], lu[4 * i + 1], lu[4 * i + 2], lu[4 * i + 3]);
            }
        } else {
            #pragma unroll
            for (int d = 0; d < 64; d++) {
                __nv_bfloat16 h = __float2bfloat16_rn(v[d]);
                size_t idx = ((size_t)b_ * DHH + d) * TT + t;
                g_Vhi[idx] = h;
                g_Vlo[idx] = __float2bfloat16_rn(v[d] - __bfloat162float(h));
            }
        }
    }

    __syncthreads();
    if (wid == 0) TC_DEALLOC(tmem, 256);
#else
    // SIMT fallback (compile-only on non-'a' pass)
    const int tid = threadIdx.x;
    const int grow = blockIdx.x * 128 + tid;
    const int b_ = grow >> 12;
    const int t  = grow & (TT - 1);
    const float4* xr = (const float4*)(x + (size_t)grow * CE);

    for (int o = 0; o < 3; o++) {
        const float* W    = (o == 0 ? Wq : (o == 1 ? Wk : Wv));
        const float* bias = (o == 0 ? bq : (o == 1 ? bk : bv));
        for (int d = 0; d < DHH; d++) {
            const float4* wr = (const float4*)(W + (size_t)d * CE);
            float acc = 0.0f;
            #pragma unroll 8
            for (int c = 0; c < CE / 4; c++) {
                float4 a = xr[c], w = wr[c];
                acc += a.x * w.x + a.y * w.y + a.z * w.z + a.w * w.w;
            }
            acc += bias[d];
            __nv_bfloat16 h = __float2bfloat16_rn(acc);
            __nv_bfloat16 l = __float2bfloat16_rn(acc - __bfloat162float(h));
            if (o == 0)      { g_Qhi[(size_t)grow * DHH + d] = h; g_Qlo[(size_t)grow * DHH + d] = l; }
            else if (o == 1) { g_Khi[(size_t)grow * DHH + d] = h; g_Klo[(size_t)grow * DHH + d] = l; }
            else {
                size_t idx = ((size_t)b_ * DHH + d) * TT + t;
                g_Vhi[idx] = h; g_Vlo[idx] = l;
            }
        }
    }
#endif
}

// ---------------------------------------------------------------------------
// Split-K causal flash attention on tcgen05.
// Per tile: S = Qhi*Khi + Qhi*Klo + Qlo*Khi (TMEM cols 0-63);
// exp+mask in registers; P split hi/lo -> SMEM;
// O += Phi*Vhi + Phi*Vlo + Plo*Vhi (TMEM cols 64-127, accumulated across tiles).
// ---------------------------------------------------------------------------
#define A_QHI 0
#define A_QLO 16384
#define A_KB  32768                 // + buf*16384 (KHI +0, KLO +8192)
#define A_VB  65536                 // + buf*16384 (VHI +0, VLO +8192)
#define A_PHI 98304
#define A_PLO 114688
#define A_CTRL 131072
#define A_MB_S (A_CTRL + 16)
#define A_MB_PV (A_CTRL + 24)
#define ATTN_SMEM 131200

__global__ __launch_bounds__(256, 1) void attn_tc_kernel()
{
    const int b = blockIdx.y;
    int xx = blockIdx.x, qi = 0, split = 0;
    for (int q = NQT - 1; q >= 0; q--) {
        int ns = (2 * q + 2 + KCHUNK - 1) / KCHUNK;
        if (xx < ns) { qi = q; split = xx; break; }
        xx -= ns;
    }
    const int nkt = 2 * qi + 2;
    const int kt0 = split * KCHUNK;
    const int kt1 = min(kt0 + KCHUNK, nkt);
    const int q0 = qi * QTILE;
    const size_t ubase = (size_t)(b * NQT + qi) * MAXSPLIT + split;

#if HAS_TC
    const __nv_bfloat16* Qhi = g_Qhi + (size_t)b * TT * DHH;
    const __nv_bfloat16* Qlo = g_Qlo + (size_t)b * TT * DHH;
    const __nv_bfloat16* Khi = g_Khi + (size_t)b * TT * DHH;
    const __nv_bfloat16* Klo = g_Klo + (size_t)b * TT * DHH;
    const __nv_bfloat16* Vhi = g_Vhi + (size_t)b * DHH * TT;
    const __nv_bfloat16* Vlo = g_Vlo + (size_t)b * DHH * TT;

    extern __shared__ char smem[];
    const uint32_t sb = (uint32_t)__cvta_generic_to_shared(smem);
    const int tid = threadIdx.x, wid = tid >> 5, lane = tid & 31;
    const int sp = wid & 3, ch = wid >> 2;
    const int row = sp * 32 + lane;

    if (wid == 0) { TC_ALLOC(sb + A_CTRL, 256); }
    else          { TC_RELINQ(); }
    __syncthreads();
    uint32_t tmem;
    asm volatile("ld.shared.b32 %0, [%1];" : "=r"(tmem) : "r"(sb + A_CTRL));
    if (tid == 0) { MBAR_INIT(sb + A_MB_S, 1); MBAR_INIT(sb + A_MB_PV, 1); }
    __syncthreads();

    auto loadQ = [&]() {
        #pragma unroll
        for (int p = 0; p < 4; p++) {
            int idx = tid + p * 256;           // 1024 = 128 rows x 8 chunks
            int r = idx >> 3, q = idx & 7;
            uint32_t off = SWZ128((uint32_t)(r * 128 + q * 16));
            const size_t src = (size_t)(q0 + r) * DHH + q * 8;
            cpa16(sb + A_QHI + off, Qhi + src);
            cpa16(sb + A_QLO + off, Qlo + src);
        }
    };
    auto loadKV = [&](int kt, int buf) {
        const int k0 = kt * KTW;
        const uint32_t kb = sb + A_KB + buf * 16384;
        const uint32_t vb = sb + A_VB + buf * 16384;
        #pragma unroll
        for (int p = 0; p < 2; p++) {
            int idx = tid + p * 256;           // 512 = 64 rows x 8 chunks
            int r = idx >> 3, q = idx & 7;
            uint32_t off = SWZ128((uint32_t)(r * 128 + q * 16));
            const size_t ks = (size_t)(k0 + r) * DHH + q * 8;
            cpa16(kb + off,        Khi + ks);
            cpa16(kb + 8192 + off, Klo + ks);
            const size_t vsrc = (size_t)r * TT + k0 + q * 8;   // r = d
            cpa16(vb + off,        Vhi + vsrc);
            cpa16(vb + 8192 + off, Vlo + vsrc);
        }
    };

    loadQ(); loadKV(kt0, 0); cpa_commit();

    float lacc = 0.0f;
    int s_ph = 0, pv_ph = 0;

    for (int kt = kt0; kt < kt1; kt++) {
        const int k0 = kt * KTW;
        const int buf = (kt - kt0) & 1;
        const bool more = (kt + 1 < kt1);
        const bool first = (kt == kt0);

        if (!first) { MBAR_WAIT(sb + A_MB_PV, pv_ph); pv_ph ^= 1; }  // prior PV done: V[buf^1], P free
        if (more) loadKV(kt + 1, buf ^ 1);
        cpa_commit();
        cpa_wait<1>();
        __syncthreads();
        FENCE_PA();

        if (wid == 0 && elect_one()) {
            const uint32_t kb = sb + A_KB + buf * 16384;
            const u64 aQhi = make_desc(sb + A_QHI), aQlo = make_desc(sb + A_QLO);
            const u64 bKhi = make_desc(kb), bKlo = make_desc(kb + 8192);
            #pragma unroll
            for (int pass = 0; pass < 3; pass++) {
                u64 ad = (pass == 2) ? aQlo : aQhi;
                u64 bd = (pass == 1) ? bKlo : bKhi;
                #pragma unroll
                for (int k = 0; k < 4; k++)
                    mma_f16_ss(tmem, ad + 2 * k, bd + 2 * k, IDESC_128x64, !(pass == 0 && k == 0));
            }
            TC_COMMIT(sb + A_MB_S);
        }
        MBAR_WAIT(sb + A_MB_S, s_ph); s_ph ^= 1;
        TC_FENCE_AFTER();

        uint32_t sr[32];
        LDTM_X32(sr, tmem + 32 * ch);
        TC_WAIT_LD();

        const int kbase = k0 + 32 * ch;
        const int qrow = q0 + row;
        const bool diag = (kt >= 2 * qi);

        uint32_t phi[16], plo[16];
        #pragma unroll
        for (int j2 = 0; j2 < 16; j2++) {
            float p0 = __expf(__uint_as_float(sr[2 * j2]));
            float p1 = __expf(__uint_as_float(sr[2 * j2 + 1]));
            if (diag) {
                if (kbase + 2 * j2     > qrow) p0 = 0.0f;
                if (kbase + 2 * j2 + 1 > qrow) p1 = 0.0f;
            }
            lacc += p0 + p1;
            split2(p0, p1, phi[j2], plo[j2]);
        }

        #pragma unroll
        for (int jj = 0; jj < 4; jj++) {
            uint32_t off = SWZ128((uint32_t)(row * 128 + ch * 64 + jj * 16));
            *(uint4*)(smem + A_PHI + off) = make_uint4(phi[4 * jj], phi[4 * jj + 1], phi[4 * jj + 2], phi[4 * jj + 3]);
            *(uint4*)(smem + A_PLO + off) = make_uint4(plo[4 * jj], plo[4 * jj + 1], plo[4 * jj + 2], plo[4 * jj + 3]);
        }
        FENCE_PA();
        __syncthreads();

        if (wid == 0 && elect_one()) {
            const uint32_t vb = sb + A_VB + buf * 16384;
            const u64 aPhi = make_desc(sb + A_PHI), aPlo = make_desc(sb + A_PLO);
            const u64 bVhi = make_desc(vb), bVlo = make_desc(vb + 8192);
            #pragma unroll
            for (int pass = 0; pass < 3; pass++) {
                u64 ad = (pass == 2) ? aPlo : aPhi;
                u64 bd = (pass == 1) ? bVlo : bVhi;
                #pragma unroll
                for (int k = 0; k < 4; k++)
                    mma_f16_ss(tmem + 64, ad + 2 * k, bd + 2 * k, IDESC_128x64,
                               !(first && pass == 0 && k == 0));
            }
            TC_COMMIT(sb + A_MB_PV);
        }
    }

    MBAR_WAIT(sb + A_MB_PV, pv_ph);
    TC_FENCE_AFTER();

    uint32_t orr[32];
    LDTM_X32(orr, tmem + 64 + 32 * ch);
    TC_WAIT_LD();

    float* Op = g_Op + ubase * (QTILE * DHH) + (size_t)row * DHH + 32 * ch;
    #pragma unroll
    for (int j4 = 0; j4 < 8; j4++)
        *(float4*)(Op + 4 * j4) = make_float4(__uint_as_float(orr[4 * j4]),
                                              __uint_as_float(orr[4 * j4 + 1]),
                                              __uint_as_float(orr[4 * j4 + 2]),
                                              __uint_as_float(orr[4 * j4 + 3]));

    float* lsm = (float*)(smem + A_PHI);    // P region free after final PV wait
    lsm[ch * 128 + row] = lacc;
    __syncthreads();
    if (ch == 0)
        g_L[ubase * QTILE + row] = lsm[row] + lsm[128 + row];

    __syncthreads();
    if (wid == 0) TC_DEALLOC(tmem, 256);
#else
    // SIMT fallback (compile-only; correct but slow)
    const int tid = threadIdx.x;
    if (tid < QTILE) {
        const int row = tid;
        const int qrow = q0 + row;
        float qv[64], o[64];
        for (int d = 0; d < 64; d++) {
            size_t idx = (size_t)(b * TT + qrow) * DHH + d;
            qv[d] = __bfloat162float(g_Qhi[idx]) + __bfloat162float(g_Qlo[idx]);
            o[d] = 0.0f;
        }
        float l = 0.0f;
        for (int kt = kt0; kt < kt1; kt++) {
            for (int c = 0; c < KTW; c++) {
                int key = kt * KTW + c;
                if (key > qrow) continue;
                float s = 0.0f;
                for (int d = 0; d < 64; d++) {
                    size_t idx = (size_t)(b * TT + key) * DHH + d;
                    s += qv[d] * (__bfloat162float(g_Khi[idx]) + __bfloat162float(g_Klo[idx]));
                }
                float p = __expf(s);
                l += p;
                for (int d = 0; d < 64; d++) {
                    size_t idx = ((size_t)b * DHH + d) * TT + key;
                    o[d] += p * (__bfloat162float(g_Vhi[idx]) + __bfloat162float(g_Vlo[idx]));
                }
            }
        }
        float* Op = g_Op + ubase * (QTILE * DHH) + (size_t)row * DHH;
        for (int d = 0; d < 64; d++) Op[d] = o[d];
        g_L[ubase * QTILE + row] = l;
    }
#endif
}

// ---------------------------------------------------------------------------
__global__ __launch_bounds__(256) void combine_kernel(float* __restrict__ out)
{
    const int qi = blockIdx.x, b = blockIdx.y;
    const int ns = (2 * qi + 2 + KCHUNK - 1) / KCHUNK;
    const int tid = threadIdx.x;
    const int r = tid >> 1;
    const int c0 = (tid & 1) * 32;
    const size_t tbase = (size_t)(b * NQT + qi) * MAXSPLIT;

    float acc[32];
    #pragma unroll
    for (int k = 0; k < 32; k++) acc[k] = 0.0f;
    float l = 0.0f;

    for (int s = 0; s < ns; s++) {
        const float* Op = g_Op + (tbase + s) * (size_t)(QTILE * DHH) + (size_t)r * DHH + c0;
        l += g_L[(tbase + s) * QTILE + r];
        #pragma unroll
        for (int j4 = 0; j4 < 8; j4++) {
            float4 v = *(const float4*)(Op + 4 * j4);
            acc[4 * j4 + 0] += v.x; acc[4 * j4 + 1] += v.y;
            acc[4 * j4 + 2] += v.z; acc[4 * j4 + 3] += v.w;
        }
    }

    const float inv = 8.0f / l;
    float* o = out + ((size_t)b * TT + (size_t)qi * QTILE + r) * DHH + c0;
    #pragma unroll
    for (int j4 = 0; j4 < 8; j4++)
        *(float4*)(o + 4 * j4) = make_float4(acc[4 * j4] * inv, acc[4 * j4 + 1] * inv,
                                             acc[4 * j4 + 2] * inv, acc[4 * j4 + 3] * inv);
}

// ---------------------------------------------------------------------------
extern "C" void kernel_launch(void* const* d_in, const int* in_sizes, int n_in,
                              void* d_out, int out_size)
{
    (void)in_sizes; (void)n_in; (void)out_size;
    const float* x  = (const float*)d_in[0];
    const float* Wq = (const float*)d_in[1];
    const float* bq = (const float*)d_in[2];
    const float* Wk = (const float*)d_in[3];
    const float* bk = (const float*)d_in[4];
    const float* Wv = (const float*)d_in[5];
    const float* bv = (const float*)d_in[6];
    float* out = (float*)d_out;

    convert_x_kernel<<<1024, 256>>>(x);
    convert_w_kernel<<<96, 256>>>(Wq, Wk, Wv);

    cudaFuncSetAttribute(qkv_tc_kernel, cudaFuncAttributeMaxDynamicSharedMemorySize, QKV_SMEM);
    qkv_tc_kernel<<<BB * TT / 128, 128, QKV_SMEM>>>(x, Wq, Wk, Wv, bq, bk, bv);

    cudaFuncSetAttribute(attn_tc_kernel, cudaFuncAttributeMaxDynamicSharedMemorySize, ATTN_SMEM);
    attn_tc_kernel<<<dim3(UNITS_PER_B, BB), 256, ATTN_SMEM>>>();

    combine_kernel<<<dim3(NQT, BB), 256>>>(out);
}

// round 15
// speedup vs baseline: 3.3962x; 1.1543x over previous
#include <cuda_runtime.h>
#include <cuda_bf16.h>
#include <cstdint>

#define BB 4
#define TT 4096
#define CE 512
#define DHH 64
#define QTILE 128
#define NQT (TT / QTILE)          // 32
#define KTW 64
#define KCHUNK 8
#define MAXSPLIT 8
#define UNITS_PER_B 144           // sum_{qi=0}^{31} ceil((2qi+2)/8)

// tcgen05 availability: only on arch-specific ('a') compilation passes.
#if defined(__CUDA_ARCH_FEAT_SM103_ALL) || defined(__CUDA_ARCH_FEAT_SM100_ALL) || defined(__CUDA_ARCH_SPECIFIC__)
#define HAS_TC 1
#else
#define HAS_TC 0
#endif

typedef unsigned long long u64;

// ---------------- scratch (__device__ globals, allocation-free) ----------------
// bf16 split operands. Q,K: [b][t][d] row-major. V: [b][d][t] transposed.
__device__ __nv_bfloat16 g_Qhi[BB * TT * DHH];
__device__ __nv_bfloat16 g_Qlo[BB * TT * DHH];
__device__ __nv_bfloat16 g_Khi[BB * TT * DHH];
__device__ __nv_bfloat16 g_Klo[BB * TT * DHH];
__device__ __nv_bfloat16 g_Vhi[BB * TT * DHH];
__device__ __nv_bfloat16 g_Vlo[BB * TT * DHH];
__device__ float g_Op[(size_t)BB * NQT * MAXSPLIT * QTILE * DHH];
__device__ float g_L[BB * NQT * MAXSPLIT * QTILE];
// bf16 split inputs for QKV GEMM
__device__ __nv_bfloat16 g_xhi[BB * TT * CE];
__device__ __nv_bfloat16 g_xlo[BB * TT * CE];
__device__ __nv_bfloat16 g_Whi[3 * DHH * CE];
__device__ __nv_bfloat16 g_Wlo[3 * DHH * CE];

// ---------------- cp.async helpers ----------------
__device__ __forceinline__ void cpa16(unsigned smem, const void* g) {
    asm volatile("cp.async.cg.shared.global [%0], [%1], 16;" :: "r"(smem), "l"(g));
}
__device__ __forceinline__ void cpa_commit() { asm volatile("cp.async.commit_group;"); }
template <int N> __device__ __forceinline__ void cpa_wait() {
    asm volatile("cp.async.wait_group %0;" :: "n"(N));
}

#define SWZ128(o) ((o) ^ (((o) >> 3) & 0x70))

// split a fp32 into bf16 hi + residual lo, packed as u32 pairs
__device__ __forceinline__ void split2(float p0, float p1, uint32_t& hu, uint32_t& lu) {
    __nv_bfloat162 hh = __floats2bfloat162_rn(p0, p1);
    hu = *reinterpret_cast<uint32_t*>(&hh);
    float h0 = __uint_as_float(hu << 16);
    float h1 = __uint_as_float(hu & 0xffff0000u);
    __nv_bfloat162 ll = __floats2bfloat162_rn(p0 - h0, p1 - h1);
    lu = *reinterpret_cast<uint32_t*>(&ll);
}

#if HAS_TC
// ---------------- tcgen05 helpers (cg1) — 'a' targets only ----------------
__device__ __forceinline__ uint32_t elect_one() {
    uint32_t p;
    asm volatile("{\n\t.reg .pred p;\n\telect.sync _|p, 0xFFFFFFFF;\n\tselp.b32 %0,1,0,p;\n\t}" : "=r"(p));
    return p;
}
__device__ __forceinline__ u64 make_desc(uint32_t saddr) {
    return ((u64)2 << 61) | ((u64)1 << 46) | ((u64)64 << 32) | ((u64)1 << 16)
         | (((u64)(saddr >> 4)) & 0x3FFF);
}
__device__ __forceinline__ void mma_f16_ss(uint32_t d, u64 ad, u64 bd, uint32_t idesc, bool en) {
    uint32_t e = en ? 1u : 0u;
    asm volatile(
        "{\n\t.reg .pred p;\n\tsetp.ne.u32 p, %5, 0;\n\t"
        "tcgen05.mma.cta_group::1.kind::f16 [%0], %1, %2, %3, {%4,%4,%4,%4}, p;\n\t}"
        :: "r"(d), "l"(ad), "l"(bd), "r"(idesc), "r"(0u), "r"(e) : "memory");
}
#define TC_ALLOC(saddr, n)  asm volatile("tcgen05.alloc.cta_group::1.sync.aligned.shared::cta.b32 [%0], %1;" :: "r"(saddr), "r"(n) : "memory")
#define TC_DEALLOC(t, n)    asm volatile("tcgen05.dealloc.cta_group::1.sync.aligned.b32 %0, %1;" :: "r"(t), "r"(n))
#define TC_RELINQ()         asm volatile("tcgen05.relinquish_alloc_permit.cta_group::1.sync.aligned;")
#define TC_COMMIT(mb)       asm volatile("tcgen05.commit.cta_group::1.mbarrier::arrive::one.shared::cluster.b64 [%0];" :: "r"(mb) : "memory")
#define TC_WAIT_LD()        asm volatile("tcgen05.wait::ld.sync.aligned;" ::: "memory")
#define TC_FENCE_AFTER()    asm volatile("tcgen05.fence::after_thread_sync;" ::: "memory")
#define MBAR_INIT(mb, n)    asm volatile("mbarrier.init.shared.b64 [%0], %1;" :: "r"(mb), "r"(n) : "memory")
#define FENCE_PA()          asm volatile("fence.proxy.async.shared::cta;" ::: "memory")

#define MBAR_WAIT(mb, par) do {                                             \
    uint32_t _mb = (mb), _p = (uint32_t)(par), _d;                          \
    asm volatile("{\n\t.reg .pred p;\n\t"                                   \
        "mbarrier.try_wait.parity.acquire.cta.shared::cta.b64 p, [%1], %2;\n\t" \
        "selp.b32 %0,1,0,p;\n\t}" : "=r"(_d) : "r"(_mb), "r"(_p) : "memory"); \
    if (!_d) {                                                              \
        asm volatile("{\n\t.reg .pred P1;\n\t"                              \
            "WL_%=:\n\t"                                                    \
            "mbarrier.try_wait.parity.acquire.cta.shared::cta.b64 P1, [%0], %1, 0x989680;\n\t" \
            "@P1 bra.uni WD_%=;\n\tbra.uni WL_%=;\n\tWD_%=:\n\t}"           \
            :: "r"(_mb), "r"(_p) : "memory");                               \
    }                                                                       \
} while (0)

#define LDTM_X32(r, t)                                                      \
    asm volatile("tcgen05.ld.sync.aligned.32x32b.x32.b32 "                  \
        "{%0,%1,%2,%3,%4,%5,%6,%7,%8,%9,%10,%11,%12,%13,%14,%15,"           \
        "%16,%17,%18,%19,%20,%21,%22,%23,%24,%25,%26,%27,%28,%29,%30,%31}, [%32];" \
        : "=r"((r)[0]),"=r"((r)[1]),"=r"((r)[2]),"=r"((r)[3]),              \
          "=r"((r)[4]),"=r"((r)[5]),"=r"((r)[6]),"=r"((r)[7]),              \
          "=r"((r)[8]),"=r"((r)[9]),"=r"((r)[10]),"=r"((r)[11]),            \
          "=r"((r)[12]),"=r"((r)[13]),"=r"((r)[14]),"=r"((r)[15]),          \
          "=r"((r)[16]),"=r"((r)[17]),"=r"((r)[18]),"=r"((r)[19]),          \
          "=r"((r)[20]),"=r"((r)[21]),"=r"((r)[22]),"=r"((r)[23]),          \
          "=r"((r)[24]),"=r"((r)[25]),"=r"((r)[26]),"=r"((r)[27]),          \
          "=r"((r)[28]),"=r"((r)[29]),"=r"((r)[30]),"=r"((r)[31])           \
        : "r"(t))
#endif // HAS_TC

// ---------------------------------------------------------------------------
// Converters (x, W -> bf16 hi/lo)
// ---------------------------------------------------------------------------
__global__ __launch_bounds__(256) void convert_x_kernel(const float* __restrict__ x)
{
    const int n4 = BB * TT * CE / 4;
    __nv_bfloat162* hi2 = reinterpret_cast<__nv_bfloat162*>(g_xhi);
    __nv_bfloat162* lo2 = reinterpret_cast<__nv_bfloat162*>(g_xlo);
    for (int i = blockIdx.x * blockDim.x + threadIdx.x; i < n4; i += gridDim.x * blockDim.x) {
        float4 v = reinterpret_cast<const float4*>(x)[i];
        uint32_t h0, l0, h1, l1;
        split2(v.x, v.y, h0, l0);
        split2(v.z, v.w, h1, l1);
        hi2[2 * i]     = *reinterpret_cast<__nv_bfloat162*>(&h0);
        hi2[2 * i + 1] = *reinterpret_cast<__nv_bfloat162*>(&h1);
        lo2[2 * i]     = *reinterpret_cast<__nv_bfloat162*>(&l0);
        lo2[2 * i + 1] = *reinterpret_cast<__nv_bfloat162*>(&l1);
    }
}

__global__ __launch_bounds__(256) void convert_w_kernel(
    const float* __restrict__ Wq, const float* __restrict__ Wk, const float* __restrict__ Wv)
{
    const int per = DHH * CE;
    const int n = 3 * per;
    for (int i = blockIdx.x * blockDim.x + threadIdx.x; i < n; i += gridDim.x * blockDim.x) {
        int o = i / per, j = i - o * per;
        float v = (o == 0 ? Wq : (o == 1 ? Wk : Wv))[j];
        __nv_bfloat16 h = __float2bfloat16_rn(v);
        g_Whi[i] = h;
        g_Wlo[i] = __float2bfloat16_rn(v - __bfloat162float(h));
    }
}

// ---------------------------------------------------------------------------
// QKV via tcgen05 (3xBF16 split) — unchanged from the 125.4us winner.
// ---------------------------------------------------------------------------
#define BUFB 81920
#define OFF_ALO 16384
#define OFF_B   32768
#define OFF_CTRL (2 * BUFB)
#define OFF_MBAR (OFF_CTRL + 16)
#define QKV_SMEM (OFF_MBAR + 48)
#define IDESC_128x64 0x8100490u    // F32 accum, bf16 x bf16, N=64, M=128

__global__ __launch_bounds__(128) void qkv_tc_kernel(
    const float* __restrict__ x,
    const float* __restrict__ Wq, const float* __restrict__ Wk, const float* __restrict__ Wv,
    const float* __restrict__ bq, const float* __restrict__ bk, const float* __restrict__ bv)
{
#if HAS_TC
    extern __shared__ char smem[];
    const uint32_t sb = (uint32_t)__cvta_generic_to_shared(smem);
    const int tid = threadIdx.x, wid = tid >> 5, lid = tid & 31;
    const int row0 = blockIdx.x * 128;

    if (wid == 0) { TC_ALLOC(sb + OFF_CTRL, 256); }
    else          { TC_RELINQ(); }
    __syncthreads();
    uint32_t tmem;
    asm volatile("ld.shared.b32 %0, [%1];" : "=r"(tmem) : "r"(sb + OFF_CTRL));
    if (tid == 0) MBAR_INIT(sb + OFF_MBAR, 1);
    __syncthreads();

    auto loadChunk = [&](int c, int buf) {
        const uint32_t base = sb + buf * BUFB;
        const int c0 = c * 64;
        #pragma unroll
        for (int p = 0; p < 8; p++) {
            int idx = tid + p * 128;
            int r = idx >> 3, q = idx & 7;
            uint32_t off = r * 128 + q * 16;
            const size_t gsrc = (size_t)(row0 + r) * CE + c0 + q * 8;
            cpa16(base + SWZ128(off), g_xhi + gsrc);
            cpa16(base + OFF_ALO + SWZ128(off), g_xlo + gsrc);
        }
        #pragma unroll
        for (int p = 0; p < 24; p++) {
            int idx = tid + p * 128;
            int t = idx >> 9, rem = idx & 511;
            int r = rem >> 3, q = rem & 7;
            uint32_t off = r * 128 + q * 16;
            const __nv_bfloat16* src = (t < 3 ? g_Whi : g_Wlo)
                + (size_t)((t % 3) * DHH + r) * CE + c0 + q * 8;
            cpa16(base + OFF_B + t * 8192 + SWZ128(off), src);
        }
    };

    loadChunk(0, 0);
    cpa_commit();

    for (int c = 0; c < 8; c++) {
        const int buf = c & 1;
        cpa_wait<0>();
        __syncthreads();
        FENCE_PA();
        if (c < 7) { loadChunk(c + 1, 1 - buf); cpa_commit(); }

        if (wid == 0 && elect_one()) {
            const uint32_t base = sb + buf * BUFB;
            const u64 ad_hi = make_desc(base);
            const u64 ad_lo = make_desc(base + OFF_ALO);
            #pragma unroll
            for (int o = 0; o < 3; o++) {
                const uint32_t dT = tmem + o * 64;
                #pragma unroll
                for (int pair = 0; pair < 3; pair++) {
                    const u64 ad = (pair == 2) ? ad_lo : ad_hi;
                    const int hl = (pair == 1) ? 1 : 0;
                    const u64 bd = make_desc(base + OFF_B + (hl * 3 + o) * 8192);
                    #pragma unroll
                    for (int k = 0; k < 4; k++)
                        mma_f16_ss(dT, ad + 2 * k, bd + 2 * k, IDESC_128x64,
                                   !(c == 0 && pair == 0 && k == 0));
                }
            }
            TC_COMMIT(sb + OFF_MBAR);
        }
        MBAR_WAIT(sb + OFF_MBAR, c & 1);
    }
    TC_FENCE_AFTER();

    const int r = wid * 32 + lid;
    const int grow = row0 + r;
    const int b_ = grow >> 12;
    const int t  = grow & (TT - 1);

    uint32_t dr[64];
    #pragma unroll
    for (int o = 0; o < 3; o++) {
        LDTM_X32(dr,      tmem + o * 64);
        LDTM_X32(dr + 32, tmem + o * 64 + 32);
        TC_WAIT_LD();
        const float* bias = (o == 0 ? bq : (o == 1 ? bk : bv));
        float v[64];
        #pragma unroll
        for (int d = 0; d < 64; d++) v[d] = __uint_as_float(dr[d]) + bias[d];

        if (o < 2) {
            uint32_t hu[32], lu[32];
            #pragma unroll
            for (int j2 = 0; j2 < 32; j2++) split2(v[2 * j2], v[2 * j2 + 1], hu[j2], lu[j2]);
            uint4* H = (uint4*)((o == 0 ? g_Qhi : g_Khi) + (size_t)grow * DHH);
            uint4* L = (uint4*)((o == 0 ? g_Qlo : g_Klo) + (size_t)grow * DHH);
            #pragma unroll
            for (int i = 0; i < 8; i++) {
                H[i] = make_uint4(hu[4 * i], hu[4 * i + 1], hu[4 * i + 2], hu[4 * i + 3]);
                L[i] = make_uint4(lu[4 * i], lu[4 * i + 1], lu[4 * i + 2], lu[4 * i + 3]);
            }
        } else {
            #pragma unroll
            for (int d = 0; d < 64; d++) {
                __nv_bfloat16 h = __float2bfloat16_rn(v[d]);
                size_t idx = ((size_t)b_ * DHH + d) * TT + t;
                g_Vhi[idx] = h;
                g_Vlo[idx] = __float2bfloat16_rn(v[d] - __bfloat162float(h));
            }
        }
    }

    __syncthreads();
    if (wid == 0) TC_DEALLOC(tmem, 256);
#else
    const int tid = threadIdx.x;
    const int grow = blockIdx.x * 128 + tid;
    const int b_ = grow >> 12;
    const int t  = grow & (TT - 1);
    const float4* xr = (const float4*)(x + (size_t)grow * CE);

    for (int o = 0; o < 3; o++) {
        const float* W    = (o == 0 ? Wq : (o == 1 ? Wk : Wv));
        const float* bias = (o == 0 ? bq : (o == 1 ? bk : bv));
        for (int d = 0; d < DHH; d++) {
            const float4* wr = (const float4*)(W + (size_t)d * CE);
            float acc = 0.0f;
            #pragma unroll 8
            for (int c = 0; c < CE / 4; c++) {
                float4 a = xr[c], w = wr[c];
                acc += a.x * w.x + a.y * w.y + a.z * w.z + a.w * w.w;
            }
            acc += bias[d];
            __nv_bfloat16 h = __float2bfloat16_rn(acc);
            __nv_bfloat16 l = __float2bfloat16_rn(acc - __bfloat162float(h));
            if (o == 0)      { g_Qhi[(size_t)grow * DHH + d] = h; g_Qlo[(size_t)grow * DHH + d] = l; }
            else if (o == 1) { g_Khi[(size_t)grow * DHH + d] = h; g_Klo[(size_t)grow * DHH + d] = l; }
            else {
                size_t idx = ((size_t)b_ * DHH + d) * TT + t;
                g_Vhi[idx] = h; g_Vlo[idx] = l;
            }
        }
    }
#endif
}

// ---------------------------------------------------------------------------
// Split-K causal flash attention on tcgen05 (round-13 skeleton + early-S).
// KV double-buffered, single P buffer, single PV mbarrier (lag-1 wait).
// S(i+1) issued immediately after LDTM of S(i) to overlap with exp/split.
// ---------------------------------------------------------------------------
#define A_QHI 0
#define A_QLO 16384
#define A_KV  32768                 // 2 bufs x 32KB: Khi+0, Klo+8K, Vhi+16K, Vlo+24K
#define A_P   98304                 // Phi+0, Plo+16K
#define A_CTRL 131072
#define A_MB_S  (A_CTRL + 16)
#define A_MB_PV (A_CTRL + 24)
#define ATTN_SMEM (A_CTRL + 64)

__global__ __launch_bounds__(256, 1) void attn_tc_kernel()
{
    const int b = blockIdx.y;
    int xx = blockIdx.x, qi = 0, split = 0;
    for (int q = NQT - 1; q >= 0; q--) {
        int ns = (2 * q + 2 + KCHUNK - 1) / KCHUNK;
        if (xx < ns) { qi = q; split = xx; break; }
        xx -= ns;
    }
    const int nkt = 2 * qi + 2;
    const int kt0 = split * KCHUNK;
    const int kt1 = min(kt0 + KCHUNK, nkt);
    const int n = kt1 - kt0;
    const int q0 = qi * QTILE;
    const size_t ubase = (size_t)(b * NQT + qi) * MAXSPLIT + split;

#if HAS_TC
    const __nv_bfloat16* Qhi = g_Qhi + (size_t)b * TT * DHH;
    const __nv_bfloat16* Qlo = g_Qlo + (size_t)b * TT * DHH;
    const __nv_bfloat16* Khi = g_Khi + (size_t)b * TT * DHH;
    const __nv_bfloat16* Klo = g_Klo + (size_t)b * TT * DHH;
    const __nv_bfloat16* Vhi = g_Vhi + (size_t)b * DHH * TT;
    const __nv_bfloat16* Vlo = g_Vlo + (size_t)b * DHH * TT;

    extern __shared__ char smem[];
    const uint32_t sb = (uint32_t)__cvta_generic_to_shared(smem);
    const int tid = threadIdx.x, wid = tid >> 5, lane = tid & 31;
    const int ch = wid >> 2;
    const int row = (wid & 3) * 32 + lane;

    if (wid == 0) { TC_ALLOC(sb + A_CTRL, 256); }
    else          { TC_RELINQ(); }
    __syncthreads();
    uint32_t tmem;
    asm volatile("ld.shared.b32 %0, [%1];" : "=r"(tmem) : "r"(sb + A_CTRL));
    if (tid == 0) { MBAR_INIT(sb + A_MB_S, 1); MBAR_INIT(sb + A_MB_PV, 1); }
    __syncthreads();

    auto loadQ = [&]() {
        #pragma unroll
        for (int p = 0; p < 4; p++) {
            int idx = tid + p * 256;           // 1024 = 128 rows x 8 chunks
            int r = idx >> 3, q = idx & 7;
            uint32_t off = SWZ128((uint32_t)(r * 128 + q * 16));
            const size_t src = (size_t)(q0 + r) * DHH + q * 8;
            cpa16(sb + A_QHI + off, Qhi + src);
            cpa16(sb + A_QLO + off, Qlo + src);
        }
    };
    auto loadKV = [&](int kt, int buf) {
        const int k0 = kt * KTW;
        const uint32_t base = sb + A_KV + buf * 32768;
        #pragma unroll
        for (int p = 0; p < 2; p++) {
            int idx = tid + p * 256;           // 512 = 64 rows x 8 chunks
            int r = idx >> 3, q = idx & 7;
            uint32_t off = SWZ128((uint32_t)(r * 128 + q * 16));
            const size_t ks = (size_t)(k0 + r) * DHH + q * 8;
            cpa16(base + off,         Khi + ks);
            cpa16(base + 8192 + off,  Klo + ks);
            const size_t vsrc = (size_t)r * TT + k0 + q * 8;   // r = d
            cpa16(base + 16384 + off, Vhi + vsrc);
            cpa16(base + 24576 + off, Vlo + vsrc);
        }
    };
    auto issueS = [&](int buf) {    // elected thread only
        const uint32_t kb = sb + A_KV + buf * 32768;
        const u64 aQhi = make_desc(sb + A_QHI), aQlo = make_desc(sb + A_QLO);
        const u64 bKhi = make_desc(kb), bKlo = make_desc(kb + 8192);
        #pragma unroll
        for (int pass = 0; pass < 3; pass++) {
            u64 ad = (pass == 2) ? aQlo : aQhi;
            u64 bd = (pass == 1) ? bKlo : bKhi;
            #pragma unroll
            for (int k = 0; k < 4; k++)
                mma_f16_ss(tmem, ad + 2 * k, bd + 2 * k, IDESC_128x64, !(pass == 0 && k == 0));
        }
        TC_COMMIT(sb + A_MB_S);
    };

    loadQ(); loadKV(kt0, 0); cpa_commit();
    cpa_wait<0>(); __syncthreads(); FENCE_PA();
    if (wid == 0 && elect_one()) issueS(0);

    float lacc = 0.0f;
    int s_ph = 0, pv_ph = 0;

    for (int i = 0; i < n; i++) {
        const int kt = kt0 + i;
        const int k0 = kt * KTW;
        const int buf = i & 1;
        const bool more = (i + 1 < n);

        // PV(i-1) done -> P buffer free, V[buf^1] free for reload
        if (i > 0) { MBAR_WAIT(sb + A_MB_PV, pv_ph); pv_ph ^= 1; }
        if (more) { loadKV(kt + 1, buf ^ 1); cpa_commit(); }

        // S(i) result
        MBAR_WAIT(sb + A_MB_S, s_ph); s_ph ^= 1;
        TC_FENCE_AFTER();
        uint32_t sr[32];
        LDTM_X32(sr, tmem + 32 * ch);
        TC_WAIT_LD();

        // S TMEM free -> issue S(i+1) once K(i+1) resident (overlaps exp below)
        if (more) {
            cpa_wait<0>();
            __syncthreads();
            FENCE_PA();
            if (wid == 0 && elect_one()) issueS(buf ^ 1);
        }

        // exp / causal mask / split
        const int kbase = k0 + 32 * ch;
        const int qrow = q0 + row;
        const bool diag = (kt >= 2 * qi);

        uint32_t phi[16], plo[16];
        #pragma unroll
        for (int j2 = 0; j2 < 16; j2++) {
            float p0 = __expf(__uint_as_float(sr[2 * j2]));
            float p1 = __expf(__uint_as_float(sr[2 * j2 + 1]));
            if (diag) {
                if (kbase + 2 * j2     > qrow) p0 = 0.0f;
                if (kbase + 2 * j2 + 1 > qrow) p1 = 0.0f;
            }
            lacc += p0 + p1;
            split2(p0, p1, phi[j2], plo[j2]);
        }

        #pragma unroll
        for (int jj = 0; jj < 4; jj++) {
            uint32_t off = SWZ128((uint32_t)(row * 128 + ch * 64 + jj * 16));
            *(uint4*)(smem + A_P + off)         = make_uint4(phi[4 * jj], phi[4 * jj + 1], phi[4 * jj + 2], phi[4 * jj + 3]);
            *(uint4*)(smem + A_P + 16384 + off) = make_uint4(plo[4 * jj], plo[4 * jj + 1], plo[4 * jj + 2], plo[4 * jj + 3]);
        }
        FENCE_PA();
        __syncthreads();

        if (wid == 0 && elect_one()) {
            const uint32_t vb = sb + A_KV + buf * 32768 + 16384;
            const u64 aPhi = make_desc(sb + A_P), aPlo = make_desc(sb + A_P + 16384);
            const u64 bVhi = make_desc(vb), bVlo = make_desc(vb + 8192);
            #pragma unroll
            for (int pass = 0; pass < 3; pass++) {
                u64 ad = (pass == 2) ? aPlo : aPhi;
                u64 bd = (pass == 1) ? bVlo : bVhi;
                #pragma unroll
                for (int k = 0; k < 4; k++)
                    mma_f16_ss(tmem + 64, ad + 2 * k, bd + 2 * k, IDESC_128x64,
                               !(i == 0 && pass == 0 && k == 0));
            }
            TC_COMMIT(sb + A_MB_PV);
        }
    }

    MBAR_WAIT(sb + A_MB_PV, pv_ph);
    TC_FENCE_AFTER();

    uint32_t orr[32];
    LDTM_X32(orr, tmem + 64 + 32 * ch);
    TC_WAIT_LD();

    float* Op = g_Op + ubase * (QTILE * DHH) + (size_t)row * DHH + 32 * ch;
    #pragma unroll
    for (int j4 = 0; j4 < 8; j4++)
        *(float4*)(Op + 4 * j4) = make_float4(__uint_as_float(orr[4 * j4]),
                                              __uint_as_float(orr[4 * j4 + 1]),
                                              __uint_as_float(orr[4 * j4 + 2]),
                                              __uint_as_float(orr[4 * j4 + 3]));

    __syncthreads();                       // all PV reads of P region done
    float* lsm = (float*)(smem + A_P);     // reuse P region for l reduction
    lsm[ch * 128 + row] = lacc;
    __syncthreads();
    if (ch == 0)
        g_L[ubase * QTILE + row] = lsm[row] + lsm[128 + row];

    __syncthreads();
    if (wid == 0) TC_DEALLOC(tmem, 256);
#else
    // SIMT fallback (compile-only; correct but slow)
    const int tid = threadIdx.x;
    if (tid < QTILE) {
        const int row = tid;
        const int qrow = q0 + row;
        float qv[64], o[64];
        for (int d = 0; d < 64; d++) {
            size_t idx = (size_t)(b * TT + qrow) * DHH + d;
            qv[d] = __bfloat162float(g_Qhi[idx]) + __bfloat162float(g_Qlo[idx]);
            o[d] = 0.0f;
        }
        float l = 0.0f;
        for (int kt = kt0; kt < kt1; kt++) {
            for (int c = 0; c < KTW; c++) {
                int key = kt * KTW + c;
                if (key > qrow) continue;
                float s = 0.0f;
                for (int d = 0; d < 64; d++) {
                    size_t idx = (size_t)(b * TT + key) * DHH + d;
                    s += qv[d] * (__bfloat162float(g_Khi[idx]) + __bfloat162float(g_Klo[idx]));
                }
                float p = __expf(s);
                l += p;
                for (int d = 0; d < 64; d++) {
                    size_t idx = ((size_t)b * DHH + d) * TT + key;
                    o[d] += p * (__bfloat162float(g_Vhi[idx]) + __bfloat162float(g_Vlo[idx]));
                }
            }
        }
        float* Op = g_Op + ubase * (QTILE * DHH) + (size_t)row * DHH;
        for (int d = 0; d < 64; d++) Op[d] = o[d];
        g_L[ubase * QTILE + row] = l;
    }
#endif
}

// ---------------------------------------------------------------------------
__global__ __launch_bounds__(256) void combine_kernel(float* __restrict__ out)
{
    const int qi = blockIdx.x, b = blockIdx.y;
    const int ns = (2 * qi + 2 + KCHUNK - 1) / KCHUNK;
    const int tid = threadIdx.x;
    const int r = tid >> 1;
    const int c0 = (tid & 1) * 32;
    const size_t tbase = (size_t)(b * NQT + qi) * MAXSPLIT;

    float acc[32];
    #pragma unroll
    for (int k = 0; k < 32; k++) acc[k] = 0.0f;
    float l = 0.0f;

    for (int s = 0; s < ns; s++) {
        const float* Op = g_Op + (tbase + s) * (size_t)(QTILE * DHH) + (size_t)r * DHH + c0;
        l += g_L[(tbase + s) * QTILE + r];
        #pragma unroll
        for (int j4 = 0; j4 < 8; j4++) {
            float4 v = *(const float4*)(Op + 4 * j4);
            acc[4 * j4 + 0] += v.x; acc[4 * j4 + 1] += v.y;
            acc[4 * j4 + 2] += v.z; acc[4 * j4 + 3] += v.w;
        }
    }

    const float inv = 8.0f / l;
    float* o = out + ((size_t)b * TT + (size_t)qi * QTILE + r) * DHH + c0;
    #pragma unroll
    for (int j4 = 0; j4 < 8; j4++)
        *(float4*)(o + 4 * j4) = make_float4(acc[4 * j4] * inv, acc[4 * j4 + 1] * inv,
                                             acc[4 * j4 + 2] * inv, acc[4 * j4 + 3] * inv);
}

// ---------------------------------------------------------------------------
extern "C" void kernel_launch(void* const* d_in, const int* in_sizes, int n_in,
                              void* d_out, int out_size)
{
    (void)in_sizes; (void)n_in; (void)out_size;
    const float* x  = (const float*)d_in[0];
    const float* Wq = (const float*)d_in[1];
    const float* bq = (const float*)d_in[2];
    const float* Wk = (const float*)d_in[3];
    const float* bk = (const float*)d_in[4];
    const float* Wv = (const float*)d_in[5];
    const float* bv = (const float*)d_in[6];
    float* out = (float*)d_out;

    convert_x_kernel<<<1024, 256>>>(x);
    convert_w_kernel<<<96, 256>>>(Wq, Wk, Wv);

    cudaFuncSetAttribute(qkv_tc_kernel, cudaFuncAttributeMaxDynamicSharedMemorySize, QKV_SMEM);
    qkv_tc_kernel<<<BB * TT / 128, 128, QKV_SMEM>>>(x, Wq, Wk, Wv, bq, bk, bv);

    cudaFuncSetAttribute(attn_tc_kernel, cudaFuncAttributeMaxDynamicSharedMemorySize, ATTN_SMEM);
    attn_tc_kernel<<<dim3(UNITS_PER_B, BB), 256, ATTN_SMEM>>>();

    combine_kernel<<<dim3(NQT, BB), 256>>>(out);
}